// round 3
// baseline (speedup 1.0000x reference)
#include <cuda_runtime.h>
#include <math.h>

#define N_NODES 16384
#define N_EDGES 262144
#define DN 256
#define DE 64
#define NH 8

// ---------------- device scratch (static allocations only) ----------------
__device__ float g_Wbig[DN * 1024];          // [256,1024]: Wn | Wv | Wq@A1q | Wk@A1k
__device__ float g_bbig[1024];               // bn | bv | bq@A1q | bk@A1k
__device__ float g_WeA[DE * DN];             // We @ A1e   [64,256]
__device__ float g_cvec[DN];                 // be@A1e + a1
__device__ float g_node[N_NODES * 1024];     // h | v | Pq | Pk  per node
__device__ float g_s[N_EDGES];               // per-edge pre-softmax score
__device__ float g_w[N_EDGES];               // softmax weights
__device__ int   g_deg[N_NODES];
__device__ int   g_off[N_NODES + 1];
__device__ int   g_cur[N_NODES];
__device__ int   g_eidx[N_EDGES];
__device__ unsigned int g_smax_u;
__device__ float g_ssum;
__device__ int   g_is64;                     // 1 if edge_index is int64, 0 if int32

__device__ __forceinline__ float lrelu(float x) { return x > 0.f ? x : 0.2f * x; }

// Index accessor parametrized by runtime-detected dtype flag.
__device__ __forceinline__ int ld_idx(const void* EI, int pos, int is64) {
    if (is64) return (int)((const long long*)EI)[pos];
    return ((const int*)EI)[pos];
}

// ---------------- dtype detection ----------------
// If edge_index is int64, every entry is in [0, N). If it's int32, an int64
// reinterpretation combines pairs (lo, hi) and is out of range unless hi==0
// (probability ~(1/16384)^256 over 256 probes -> effectively impossible).
__global__ void k_detect(const void* EI) {
    __shared__ int bad;
    if (threadIdx.x == 0) bad = 0;
    __syncthreads();
    long long v = ((const long long*)EI)[threadIdx.x];   // first 2KB, in-bounds either way
    if (v < 0 || v >= N_NODES) atomicOr(&bad, 1);
    __syncthreads();
    if (threadIdx.x == 0) g_is64 = bad ? 0 : 1;
}

// ---------------- init ----------------
__global__ void k_init() {
    int i = blockIdx.x * blockDim.x + threadIdx.x;
    if (i < N_NODES) { g_deg[i] = 0; g_cur[i] = 0; }
    if (i == 0) { g_smax_u = 0u; g_ssum = 0.f; }
}

// ---------------- weight prep: copy Wn/Wv ----------------
__global__ void k_prep_copy(const float* __restrict__ Wn, const float* __restrict__ bn,
                            const float* __restrict__ Wv, const float* __restrict__ bv) {
    int i = blockIdx.x * blockDim.x + threadIdx.x;
    if (i < DN * 512) {
        int k = i >> 9, j = i & 511;
        g_Wbig[k * 1024 + j] = (j < 256) ? Wn[k * 256 + j] : Wv[k * 256 + j - 256];
    }
    if (i < 512) g_bbig[i] = (i < 256) ? bn[i] : bv[i - 256];
}

// ---------------- weight prep: fold A1 into Wq/Wk/We and biases ----------------
__global__ void k_prep_fold(const float* __restrict__ Wq, const float* __restrict__ bq,
                            const float* __restrict__ Wk, const float* __restrict__ bk,
                            const float* __restrict__ We, const float* __restrict__ be,
                            const float* __restrict__ A1, const float* __restrict__ a1) {
    int i = blockIdx.x * blockDim.x + threadIdx.x;
    if (i < 65536) {                        // WqA [256,256]
        int k = i >> 8, j = i & 255;
        float s = 0.f;
        for (int m = 0; m < 256; m++) s += Wq[k * 256 + m] * A1[m * 256 + j];
        g_Wbig[k * 1024 + 512 + j] = s;
    } else if (i < 131072) {                // WkA [256,256]
        int t = i - 65536; int k = t >> 8, j = t & 255;
        float s = 0.f;
        for (int m = 0; m < 256; m++) s += Wk[k * 256 + m] * A1[(256 + m) * 256 + j];
        g_Wbig[k * 1024 + 768 + j] = s;
    } else if (i < 131072 + 16384) {        // WeA [64,256]
        int t = i - 131072; int k = t >> 8, j = t & 255;
        float s = 0.f;
        for (int m = 0; m < 256; m++) s += We[k * 256 + m] * A1[(512 + m) * 256 + j];
        g_WeA[k * 256 + j] = s;
    } else if (i < 131072 + 16384 + 256) {  // bq @ A1q
        int j = i - (131072 + 16384);
        float s = 0.f;
        for (int m = 0; m < 256; m++) s += bq[m] * A1[m * 256 + j];
        g_bbig[512 + j] = s;
    } else if (i < 131072 + 16384 + 512) {  // bk @ A1k
        int j = i - (131072 + 16384 + 256);
        float s = 0.f;
        for (int m = 0; m < 256; m++) s += bk[m] * A1[(256 + m) * 256 + j];
        g_bbig[768 + j] = s;
    } else if (i < 131072 + 16384 + 768) {  // be @ A1e + a1
        int j = i - (131072 + 16384 + 512);
        float s = 0.f;
        for (int m = 0; m < 256; m++) s += be[m] * A1[(512 + m) * 256 + j];
        g_cvec[j] = s + a1[j];
    }
}

// ---------------- node GEMM: [16384,256] @ [256,1024] + bias -> g_node ----------------
__global__ void __launch_bounds__(256) k_node_gemm(const float* __restrict__ X) {
    __shared__ float As[16][128];
    __shared__ float Bs[16][128];
    int bx = blockIdx.x, by = blockIdx.y;
    int tid = threadIdx.x;
    int tx = tid & 15, ty = tid >> 4;
    float acc[8][8];
#pragma unroll
    for (int i = 0; i < 8; i++)
#pragma unroll
        for (int j = 0; j < 8; j++) acc[i][j] = 0.f;

    const float* Ap = X + by * 128 * 256;
    const float* Bp = g_Wbig + bx * 128;

    for (int k0 = 0; k0 < 256; k0 += 16) {
#pragma unroll
        for (int i = 0; i < 2; i++) {
            int lin = i * 256 + tid;
            int row = lin >> 2, kf = lin & 3;
            float4 v = *(const float4*)(Ap + row * 256 + k0 + kf * 4);
            As[kf * 4 + 0][row] = v.x; As[kf * 4 + 1][row] = v.y;
            As[kf * 4 + 2][row] = v.z; As[kf * 4 + 3][row] = v.w;
        }
#pragma unroll
        for (int i = 0; i < 2; i++) {
            int lin = i * 256 + tid;
            int row = lin >> 5, cf = lin & 31;
            *(float4*)(&Bs[row][cf * 4]) = *(const float4*)(Bp + (k0 + row) * 1024 + cf * 4);
        }
        __syncthreads();
#pragma unroll
        for (int k = 0; k < 16; k++) {
            float a[8], bb[8];
            *(float4*)(a)     = *(float4*)(&As[k][ty * 8]);
            *(float4*)(a + 4) = *(float4*)(&As[k][ty * 8 + 4]);
            *(float4*)(bb)     = *(float4*)(&Bs[k][tx * 8]);
            *(float4*)(bb + 4) = *(float4*)(&Bs[k][tx * 8 + 4]);
#pragma unroll
            for (int i = 0; i < 8; i++)
#pragma unroll
                for (int j = 0; j < 8; j++) acc[i][j] += a[i] * bb[j];
        }
        __syncthreads();
    }
#pragma unroll
    for (int i = 0; i < 8; i++) {
        int row = by * 128 + ty * 8 + i;
        float* dst = g_node + row * 1024 + bx * 128 + tx * 8;
        const float* bb = g_bbig + bx * 128 + tx * 8;
#pragma unroll
        for (int j = 0; j < 8; j++) dst[j] = acc[i][j] + bb[j];
    }
}

// ---------------- fused edge kernel: Pe GEMM + gather + leaky + A2 + head mean ----------------
// block = 256 threads = 8 warps; warp handles 8 edges; lane covers dims l*4..l*4+3 and 128+l*4..
__global__ void __launch_bounds__(256) k_edge(const float* __restrict__ EF,
                                              const void* __restrict__ EI,
                                              const float* __restrict__ A2,
                                              const float* __restrict__ a2) {
    __shared__ float sEF[64][64];
    __shared__ float sA2T[8][256];
    __shared__ float sc[256];
    __shared__ float sa2[8];
    int tid = threadIdx.x;
    int b = blockIdx.x;
    int is64 = g_is64;
#pragma unroll
    for (int i = 0; i < 4; i++) {
        int lin = i * 256 + tid;              // float4 index, 1024 total
        int row = lin >> 4, c4 = lin & 15;
        float4 v = ((const float4*)(EF + ((size_t)b * 64 + row) * 64))[c4];
        ((float4*)(&sEF[row][0]))[c4] = v;
    }
#pragma unroll
    for (int i = 0; i < 8; i++) {
        int lin = i * 256 + tid;
        sA2T[lin & 7][lin >> 3] = A2[lin];
    }
    sc[tid] = g_cvec[tid];
    if (tid < 8) sa2[tid] = a2[tid];
    __syncthreads();

    int w = tid >> 5, l = tid & 31;
    float acc[8][8];
#pragma unroll
    for (int e = 0; e < 8; e++)
#pragma unroll
        for (int d = 0; d < 8; d++) acc[e][d] = 0.f;

#pragma unroll 4
    for (int k = 0; k < 64; k++) {
        float4 w0 = *(const float4*)(g_WeA + k * 256 + l * 4);
        float4 w1 = *(const float4*)(g_WeA + k * 256 + 128 + l * 4);
#pragma unroll
        for (int e = 0; e < 8; e++) {
            float f = sEF[(w << 3) + e][k];
            acc[e][0] += f * w0.x; acc[e][1] += f * w0.y;
            acc[e][2] += f * w0.z; acc[e][3] += f * w0.w;
            acc[e][4] += f * w1.x; acc[e][5] += f * w1.y;
            acc[e][6] += f * w1.z; acc[e][7] += f * w1.w;
        }
    }

    float4 c0 = *(float4*)(&sc[l * 4]);
    float4 c1 = *(float4*)(&sc[128 + l * 4]);
    int eb = b * 64 + (w << 3);
#pragma unroll
    for (int e = 0; e < 8; e++) {
        int eg = eb + e;
        int sn = ld_idx(EI, eg, is64);
        int tn = ld_idx(EI, N_EDGES + eg, is64);
        const float* pq = g_node + sn * 1024 + 512;
        const float* pk = g_node + tn * 1024 + 768;
        float4 q0 = *(const float4*)(pq + l * 4);
        float4 q1 = *(const float4*)(pq + 128 + l * 4);
        float4 p0 = *(const float4*)(pk + l * 4);
        float4 p1 = *(const float4*)(pk + 128 + l * 4);
        float z[8];
        z[0] = lrelu(acc[e][0] + q0.x + p0.x + c0.x);
        z[1] = lrelu(acc[e][1] + q0.y + p0.y + c0.y);
        z[2] = lrelu(acc[e][2] + q0.z + p0.z + c0.z);
        z[3] = lrelu(acc[e][3] + q0.w + p0.w + c0.w);
        z[4] = lrelu(acc[e][4] + q1.x + p1.x + c1.x);
        z[5] = lrelu(acc[e][5] + q1.y + p1.y + c1.y);
        z[6] = lrelu(acc[e][6] + q1.z + p1.z + c1.z);
        z[7] = lrelu(acc[e][7] + q1.w + p1.w + c1.w);
        float ha[8];
#pragma unroll
        for (int h = 0; h < 8; h++) {
            float4 A0 = *(float4*)(&sA2T[h][l * 4]);
            float4 B0 = *(float4*)(&sA2T[h][128 + l * 4]);
            ha[h] = z[0] * A0.x + z[1] * A0.y + z[2] * A0.z + z[3] * A0.w
                  + z[4] * B0.x + z[5] * B0.y + z[6] * B0.z + z[7] * B0.w;
        }
#pragma unroll
        for (int off = 16; off; off >>= 1)
#pragma unroll
            for (int h = 0; h < 8; h++) ha[h] += __shfl_xor_sync(0xffffffffu, ha[h], off);
        if (l == 0) {
            float s = 0.f;
#pragma unroll
            for (int h = 0; h < 8; h++) s += lrelu(ha[h] + sa2[h]);
            g_s[eg] = s * 0.125f;
        }
    }
}

// ---------------- softmax reductions ----------------
__device__ __forceinline__ unsigned f2u_ord(float f) {
    unsigned u = __float_as_uint(f);
    return (u & 0x80000000u) ? ~u : (u | 0x80000000u);
}
__device__ __forceinline__ float u2f_ord(unsigned u) {
    return (u & 0x80000000u) ? __uint_as_float(u ^ 0x80000000u) : __uint_as_float(~u);
}

__global__ void k_smax() {
    float m = -3.4e38f;
    for (int i = blockIdx.x * blockDim.x + threadIdx.x; i < N_EDGES; i += gridDim.x * blockDim.x)
        m = fmaxf(m, g_s[i]);
#pragma unroll
    for (int off = 16; off; off >>= 1) m = fmaxf(m, __shfl_xor_sync(0xffffffffu, m, off));
    __shared__ float sm[8];
    if ((threadIdx.x & 31) == 0) sm[threadIdx.x >> 5] = m;
    __syncthreads();
    if (threadIdx.x == 0) {
        for (int i = 1; i < 8; i++) m = fmaxf(m, sm[i]);
        atomicMax(&g_smax_u, f2u_ord(m));
    }
}

__global__ void k_ssum() {
    float mx = u2f_ord(g_smax_u);
    float s = 0.f;
    for (int i = blockIdx.x * blockDim.x + threadIdx.x; i < N_EDGES; i += gridDim.x * blockDim.x)
        s += expf(g_s[i] - mx);
#pragma unroll
    for (int off = 16; off; off >>= 1) s += __shfl_xor_sync(0xffffffffu, s, off);
    __shared__ float sm[8];
    if ((threadIdx.x & 31) == 0) sm[threadIdx.x >> 5] = s;
    __syncthreads();
    if (threadIdx.x == 0) {
        for (int i = 1; i < 8; i++) s += sm[i];
        atomicAdd(&g_ssum, s);
    }
}

__global__ void k_wnorm() {
    int i = blockIdx.x * blockDim.x + threadIdx.x;
    if (i < N_EDGES) {
        float mx = u2f_ord(g_smax_u);
        g_w[i] = expf(g_s[i] - mx) / g_ssum;
    }
}

// ---------------- counting sort by src ----------------
__global__ void k_hist(const void* __restrict__ EI) {
    int e = blockIdx.x * blockDim.x + threadIdx.x;
    int is64 = g_is64;
    if (e < N_EDGES) atomicAdd(&g_deg[ld_idx(EI, e, is64)], 1);
}

__global__ void k_scan() {
    int tid = threadIdx.x;
    int x[16];
    int base = tid * 16;
    int tot = 0;
#pragma unroll
    for (int i = 0; i < 16; i++) { x[i] = g_deg[base + i]; tot += x[i]; }
    int v = tot;
#pragma unroll
    for (int off = 1; off < 32; off <<= 1) {
        int t = __shfl_up_sync(0xffffffffu, v, off);
        if ((tid & 31) >= off) v += t;
    }
    __shared__ int sw[32];
    if ((tid & 31) == 31) sw[tid >> 5] = v;
    __syncthreads();
    if (tid < 32) {
        int t = sw[tid];
        int v2 = t;
#pragma unroll
        for (int off = 1; off < 32; off <<= 1) {
            int u = __shfl_up_sync(0xffffffffu, v2, off);
            if (tid >= off) v2 += u;
        }
        sw[tid] = v2 - t;  // exclusive warp offsets
    }
    __syncthreads();
    int run = sw[tid >> 5] + v - tot;  // block-level exclusive prefix for this thread
#pragma unroll
    for (int i = 0; i < 16; i++) { g_off[base + i] = run; run += x[i]; }
    if (tid == 1023) g_off[N_NODES] = run;
}

__global__ void k_place(const void* __restrict__ EI) {
    int e = blockIdx.x * blockDim.x + threadIdx.x;
    int is64 = g_is64;
    if (e < N_EDGES) {
        int sn = ld_idx(EI, e, is64);
        int p = atomicAdd(&g_cur[sn], 1);
        g_eidx[g_off[sn] + p] = e;
    }
}

// ---------------- final: gather w*v[tgt], add h, LayerNorm ----------------
__global__ void __launch_bounds__(256) k_final(const void* __restrict__ EI,
                                               const float* __restrict__ gamma,
                                               const float* __restrict__ beta,
                                               float* __restrict__ out) {
    int n = blockIdx.x;
    int d = threadIdx.x;
    int is64 = g_is64;
    float acc = g_node[n * 1024 + d];  // h
    int beg = g_off[n], end = g_off[n + 1];
    for (int i = beg; i < end; i++) {
        int e = g_eidx[i];
        int t = ld_idx(EI, N_EDGES + e, is64);
        acc += g_w[e] * g_node[t * 1024 + 256 + d];  // v
    }
    float v1 = acc, v2 = acc * acc;
#pragma unroll
    for (int off = 16; off; off >>= 1) {
        v1 += __shfl_xor_sync(0xffffffffu, v1, off);
        v2 += __shfl_xor_sync(0xffffffffu, v2, off);
    }
    __shared__ float s1[8], s2[8];
    __shared__ float s_mu, s_rstd;
    int wid = d >> 5, lane = d & 31;
    if (lane == 0) { s1[wid] = v1; s2[wid] = v2; }
    __syncthreads();
    if (d == 0) {
        float S = 0.f, Q = 0.f;
        for (int i = 0; i < 8; i++) { S += s1[i]; Q += s2[i]; }
        float mu = S * (1.f / 256.f);
        float var = Q * (1.f / 256.f) - mu * mu;
        s_mu = mu;
        s_rstd = rsqrtf(var + 1e-5f);
    }
    __syncthreads();
    out[n * 256 + d] = (acc - s_mu) * s_rstd * gamma[d] + beta[d];
}

// ---------------- launch ----------------
extern "C" void kernel_launch(void* const* d_in, const int* in_sizes, int n_in,
                              void* d_out, int out_size) {
    const float* X     = (const float*)d_in[0];
    const void*  EI    = d_in[1];
    const float* EF    = (const float*)d_in[2];
    const float* Wn    = (const float*)d_in[3];
    const float* bn    = (const float*)d_in[4];
    const float* Wq    = (const float*)d_in[5];
    const float* bq    = (const float*)d_in[6];
    const float* Wk    = (const float*)d_in[7];
    const float* bk    = (const float*)d_in[8];
    const float* Wv    = (const float*)d_in[9];
    const float* bv    = (const float*)d_in[10];
    const float* We    = (const float*)d_in[11];
    const float* be    = (const float*)d_in[12];
    const float* A1    = (const float*)d_in[13];
    const float* a1    = (const float*)d_in[14];
    const float* A2    = (const float*)d_in[15];
    const float* a2    = (const float*)d_in[16];
    const float* gamma = (const float*)d_in[17];
    const float* beta  = (const float*)d_in[18];
    float* out = (float*)d_out;

    k_detect<<<1, 256>>>(EI);
    k_init<<<64, 256>>>();
    k_prep_copy<<<512, 256>>>(Wn, bn, Wv, bv);
    k_prep_fold<<<579, 256>>>(Wq, bq, Wk, bk, We, be, A1, a1);
    k_node_gemm<<<dim3(8, 128), 256>>>(X);
    k_edge<<<4096, 256>>>(EF, EI, A2, a2);
    k_smax<<<256, 256>>>();
    k_ssum<<<256, 256>>>();
    k_wnorm<<<1024, 256>>>();
    k_hist<<<1024, 256>>>(EI);
    k_scan<<<1, 1024>>>();
    k_place<<<1024, 256>>>(EI);
    k_final<<<16384, 256>>>(EI, gamma, beta, out);
}

// round 4
// speedup vs baseline: 2.3264x; 2.3264x over previous
#include <cuda_runtime.h>
#include <cuda_bf16.h>
#include <math.h>
#include <stdint.h>

#define N_NODES 16384
#define N_EDGES 262144
#define DN 256
#define DE 64
#define NH 8

typedef __nv_bfloat16 bf16;
typedef __nv_bfloat162 bf162;

// ---------------- device scratch (static allocations only) ----------------
__device__ float g_Wbig[DN * 1024];            // [256,1024]: Wn | Wv | Wq@A1q | Wk@A1k
__device__ float g_bbig[1024];                 // bn | bv | bqA | bkA
__device__ float g_WeA[DE * DN];               // We @ A1e   [64,256]
__device__ float g_cvec[DN];                   // be@A1e + a1
__device__ bf16  g_WThi[1024 * 256];           // W transposed [n][k] hi
__device__ bf16  g_WTlo[1024 * 256];           // lo
__device__ bf16  g_Xhi[N_NODES * 256];
__device__ bf16  g_Xlo[N_NODES * 256];
__device__ bf16  g_WeATb[256 * 64];            // WeA transposed [n][k] bf16
__device__ bf16  g_A2Tb[8 * 256];              // A2 transposed [h][d] bf16
__device__ float g_node[N_NODES * 512];        // h | v   (fp32)
__device__ bf16  g_nodeqk[N_NODES * 512];      // Pq | Pk (bf16)
__device__ float g_s[N_EDGES];                 // per-edge pre-softmax score
__device__ int   g_deg[N_NODES];
__device__ int   g_off[N_NODES + 1];
__device__ int   g_cur[N_NODES];
__device__ int   g_eidx[N_EDGES];
__device__ unsigned int g_smax_u;
__device__ float g_ssum;
__device__ int   g_is64;

__device__ __forceinline__ float lrelu(float x) { return x > 0.f ? x : 0.2f * x; }

__device__ __forceinline__ int ld_idx(const void* EI, int pos, int is64) {
    if (is64) return (int)((const long long*)EI)[pos];
    return ((const int*)EI)[pos];
}

__device__ __forceinline__ uint32_t pack_bf16(float x, float y) {
    bf162 p = __floats2bfloat162_rn(x, y);
    return *reinterpret_cast<uint32_t*>(&p);
}

__device__ __forceinline__ void mma16816(float* d, uint32_t a0, uint32_t a1, uint32_t a2, uint32_t a3,
                                         uint32_t b0, uint32_t b1) {
    asm volatile(
        "mma.sync.aligned.m16n8k16.row.col.f32.bf16.bf16.f32 "
        "{%0,%1,%2,%3},{%4,%5,%6,%7},{%8,%9},{%0,%1,%2,%3};"
        : "+f"(d[0]), "+f"(d[1]), "+f"(d[2]), "+f"(d[3])
        : "r"(a0), "r"(a1), "r"(a2), "r"(a3), "r"(b0), "r"(b1));
}

__device__ __forceinline__ uint32_t smem_u32(const void* p) {
    return (uint32_t)__cvta_generic_to_shared(p);
}
#define CP16(dst, src) asm volatile("cp.async.ca.shared.global [%0], [%1], 16;\n" :: "r"(dst), "l"(src))

// ---------------- dtype detection ----------------
__global__ void k_detect(const void* EI) {
    __shared__ int bad;
    if (threadIdx.x == 0) bad = 0;
    __syncthreads();
    long long v = ((const long long*)EI)[threadIdx.x];
    if (v < 0 || v >= N_NODES) atomicOr(&bad, 1);
    __syncthreads();
    if (threadIdx.x == 0) g_is64 = bad ? 0 : 1;
}

// ---------------- init ----------------
__global__ void k_init() {
    int i = blockIdx.x * blockDim.x + threadIdx.x;
    if (i < N_NODES) { g_deg[i] = 0; g_cur[i] = 0; }
    if (i == 0) { g_smax_u = 0u; g_ssum = 0.f; }
}

// ---------------- weight prep: copy Wn/Wv ----------------
__global__ void k_prep_copy(const float* __restrict__ Wn, const float* __restrict__ bn,
                            const float* __restrict__ Wv, const float* __restrict__ bv) {
    int i = blockIdx.x * blockDim.x + threadIdx.x;
    if (i < DN * 512) {
        int k = i >> 9, j = i & 511;
        g_Wbig[k * 1024 + j] = (j < 256) ? Wn[k * 256 + j] : Wv[k * 256 + j - 256];
    }
    if (i < 512) g_bbig[i] = (i < 256) ? bn[i] : bv[i - 256];
}

// ---------------- weight prep: fold A1 into Wq/Wk/We and biases ----------------
__global__ void k_prep_fold(const float* __restrict__ Wq, const float* __restrict__ bq,
                            const float* __restrict__ Wk, const float* __restrict__ bk,
                            const float* __restrict__ We, const float* __restrict__ be,
                            const float* __restrict__ A1, const float* __restrict__ a1) {
    int i = blockIdx.x * blockDim.x + threadIdx.x;
    if (i < 65536) {
        int k = i >> 8, j = i & 255;
        float s = 0.f;
#pragma unroll 8
        for (int m = 0; m < 256; m++) s += Wq[k * 256 + m] * A1[m * 256 + j];
        g_Wbig[k * 1024 + 512 + j] = s;
    } else if (i < 131072) {
        int t = i - 65536; int k = t >> 8, j = t & 255;
        float s = 0.f;
#pragma unroll 8
        for (int m = 0; m < 256; m++) s += Wk[k * 256 + m] * A1[(256 + m) * 256 + j];
        g_Wbig[k * 1024 + 768 + j] = s;
    } else if (i < 131072 + 16384) {
        int t = i - 131072; int k = t >> 8, j = t & 255;
        float s = 0.f;
#pragma unroll 8
        for (int m = 0; m < 256; m++) s += We[k * 256 + m] * A1[(512 + m) * 256 + j];
        g_WeA[k * 256 + j] = s;
    } else if (i < 131072 + 16384 + 256) {
        int j = i - (131072 + 16384);
        float s = 0.f;
        for (int m = 0; m < 256; m++) s += bq[m] * A1[m * 256 + j];
        g_bbig[512 + j] = s;
    } else if (i < 131072 + 16384 + 512) {
        int j = i - (131072 + 16384 + 256);
        float s = 0.f;
        for (int m = 0; m < 256; m++) s += bk[m] * A1[(256 + m) * 256 + j];
        g_bbig[768 + j] = s;
    } else if (i < 131072 + 16384 + 768) {
        int j = i - (131072 + 16384 + 512);
        float s = 0.f;
        for (int m = 0; m < 256; m++) s += be[m] * A1[(512 + m) * 256 + j];
        g_cvec[j] = s + a1[j];
    }
}

// ---------------- conversions ----------------
__global__ void k_convX(const float* __restrict__ X) {
    int i = blockIdx.x * blockDim.x + threadIdx.x;   // over 16384*256
    float w = X[i];
    bf16 hi = __float2bfloat16_rn(w);
    g_Xhi[i] = hi;
    g_Xlo[i] = __float2bfloat16_rn(w - __bfloat162float(hi));
}

__global__ void k_convW(const float* __restrict__ A2) {
    int i = blockIdx.x * blockDim.x + threadIdx.x;
    if (i < 1024 * 256) {                     // WT split: [n][k]
        int n = i >> 8, k = i & 255;
        float w = g_Wbig[k * 1024 + n];
        bf16 hi = __float2bfloat16_rn(w);
        g_WThi[n * 256 + k] = hi;
        g_WTlo[n * 256 + k] = __float2bfloat16_rn(w - __bfloat162float(hi));
    } else if (i < 1024 * 256 + 256 * 64) {   // WeAT [n=256][k=64]
        int t = i - 1024 * 256;
        int n = t >> 6, k = t & 63;
        g_WeATb[t] = __float2bfloat16_rn(g_WeA[k * 256 + n]);
    } else if (i < 1024 * 256 + 256 * 64 + 8 * 256) {  // A2T [h][d]
        int t = i - (1024 * 256 + 256 * 64);
        int h = t >> 8, d = t & 255;
        g_A2Tb[t] = __float2bfloat16_rn(A2[d * 8 + h]);
    }
}

// ---------------- node GEMM (tensor cores, split bf16, 3 mma passes) -------
// C[16384,1024] = X[16384,256(fp32 via hi/lo)] @ W[256,1024]
// grid (8 n-blocks, 128 m-blocks), 256 threads (8 warps as 4m x 2n)
// warp tile m32 x n64, k-chunk 32, cp.async double buffered.
#define NGM_SMEM (2 * 4 * 128 * 40 * 2)   // 81920 bytes

__global__ void __launch_bounds__(256) k_node_gemm() {
    extern __shared__ bf16 smN[];
    const int tid = threadIdx.x;
    const int lane = tid & 31, wid = tid >> 5;
    const int wm = wid & 3, wn = wid >> 2;
    const int m0 = blockIdx.y * 128, n0 = blockIdx.x * 128;

    float acc[2][8][4];
#pragma unroll
    for (int mt = 0; mt < 2; mt++)
#pragma unroll
        for (int nt = 0; nt < 8; nt++)
#pragma unroll
            for (int c = 0; c < 4; c++) acc[mt][nt][c] = 0.f;

    // loader lambda via macro-ish function
    auto load_chunk = [&](int c, int buf) {
        int k0 = c * 32;
#pragma unroll
        for (int j = 0; j < 8; j++) {
            int id = j * 256 + tid;
            int arr = id >> 9;
            int rem = id & 511;
            int row = rem >> 2, seg = rem & 3;
            const bf16* src;
            if (arr == 0)      src = g_Xhi  + (m0 + row) * 256 + k0 + seg * 8;
            else if (arr == 1) src = g_Xlo  + (m0 + row) * 256 + k0 + seg * 8;
            else if (arr == 2) src = g_WThi + (n0 + row) * 256 + k0 + seg * 8;
            else               src = g_WTlo + (n0 + row) * 256 + k0 + seg * 8;
            uint32_t dst = smem_u32(smN + buf * 20480 + arr * 5120 + row * 40 + seg * 8);
            CP16(dst, src);
        }
        asm volatile("cp.async.commit_group;\n" ::);
    };

    load_chunk(0, 0);

    for (int c = 0; c < 8; c++) {
        if (c < 7) load_chunk(c + 1, (c + 1) & 1);
        if (c < 7) asm volatile("cp.async.wait_group 1;\n" ::);
        else       asm volatile("cp.async.wait_group 0;\n" ::);
        __syncthreads();

        const int bb = (c & 1) * 20480;
        const bf16* sAh = smN + bb;
        const bf16* sAl = smN + bb + 5120;
        const bf16* sBh = smN + bb + 2 * 5120;
        const bf16* sBl = smN + bb + 3 * 5120;

#pragma unroll
        for (int kh = 0; kh < 2; kh++) {
            const int kc = kh * 16 + (lane & 3) * 2;
            uint32_t Ah[2][4], Al[2][4], Bh[8][2], Bl[8][2];
#pragma unroll
            for (int mt = 0; mt < 2; mt++) {
                int r = wm * 32 + mt * 16 + (lane >> 2);
                Ah[mt][0] = *(const uint32_t*)(sAh + r * 40 + kc);
                Ah[mt][1] = *(const uint32_t*)(sAh + (r + 8) * 40 + kc);
                Ah[mt][2] = *(const uint32_t*)(sAh + r * 40 + kc + 8);
                Ah[mt][3] = *(const uint32_t*)(sAh + (r + 8) * 40 + kc + 8);
                Al[mt][0] = *(const uint32_t*)(sAl + r * 40 + kc);
                Al[mt][1] = *(const uint32_t*)(sAl + (r + 8) * 40 + kc);
                Al[mt][2] = *(const uint32_t*)(sAl + r * 40 + kc + 8);
                Al[mt][3] = *(const uint32_t*)(sAl + (r + 8) * 40 + kc + 8);
            }
#pragma unroll
            for (int nt = 0; nt < 8; nt++) {
                int n = wn * 64 + nt * 8 + (lane >> 2);
                Bh[nt][0] = *(const uint32_t*)(sBh + n * 40 + kc);
                Bh[nt][1] = *(const uint32_t*)(sBh + n * 40 + kc + 8);
                Bl[nt][0] = *(const uint32_t*)(sBl + n * 40 + kc);
                Bl[nt][1] = *(const uint32_t*)(sBl + n * 40 + kc + 8);
            }
#pragma unroll
            for (int mt = 0; mt < 2; mt++)
#pragma unroll
                for (int nt = 0; nt < 8; nt++) {
                    mma16816(acc[mt][nt], Ah[mt][0], Ah[mt][1], Ah[mt][2], Ah[mt][3], Bh[nt][0], Bh[nt][1]);
                    mma16816(acc[mt][nt], Ah[mt][0], Ah[mt][1], Ah[mt][2], Ah[mt][3], Bl[nt][0], Bl[nt][1]);
                    mma16816(acc[mt][nt], Al[mt][0], Al[mt][1], Al[mt][2], Al[mt][3], Bh[nt][0], Bh[nt][1]);
                }
        }
        __syncthreads();
    }

    // epilogue: n<512 -> g_node fp32 (h|v); n>=512 -> g_nodeqk bf16 (Pq|Pk)
#pragma unroll
    for (int mt = 0; mt < 2; mt++) {
        int r0 = m0 + wm * 32 + mt * 16 + (lane >> 2);
#pragma unroll
        for (int nt = 0; nt < 8; nt++) {
            int colg = n0 + wn * 64 + nt * 8 + (lane & 3) * 2;
            float b0 = g_bbig[colg], b1 = g_bbig[colg + 1];
            float c0 = acc[mt][nt][0] + b0, c1 = acc[mt][nt][1] + b1;
            float c2 = acc[mt][nt][2] + b0, c3 = acc[mt][nt][3] + b1;
            if (colg < 512) {
                *(float2*)(g_node + r0 * 512 + colg) = make_float2(c0, c1);
                *(float2*)(g_node + (r0 + 8) * 512 + colg) = make_float2(c2, c3);
            } else {
                *(bf162*)(g_nodeqk + r0 * 512 + colg - 512) = __floats2bfloat162_rn(c0, c1);
                *(bf162*)(g_nodeqk + (r0 + 8) * 512 + colg - 512) = __floats2bfloat162_rn(c2, c3);
            }
        }
    }
}

// ---------------- fused edge kernel (tensor cores) -------------------------
// CTA: 256 thr / 8 warps, 128 edges (16 per warp). GEMM1: EF@WeA (k=64,n=256)
// -> z = lrelu(+Pq[src]+Pk[tgt]+c) -> GEMM2: z@A2 (k=256,n=8) -> lrelu+mean.
#define E_SEF   0
#define E_SWT   18432
#define E_SA2T  55296
#define E_SC    59520
#define E_SA2   60544
#define E_SSRC  60576
#define E_STGT  61088
#define EDGE_SMEM 61600

__global__ void __launch_bounds__(256) k_edge(const float* __restrict__ EF,
                                              const void* __restrict__ EI,
                                              const float* __restrict__ a2) {
    extern __shared__ char smE[];
    bf16*  sEF  = (bf16*)(smE + E_SEF);     // [128][72]
    bf16*  sWT  = (bf16*)(smE + E_SWT);     // [256][72]
    bf16*  sA2T = (bf16*)(smE + E_SA2T);    // [8][264]
    float* sc   = (float*)(smE + E_SC);
    float* sa2  = (float*)(smE + E_SA2);
    int*   ssrc = (int*)(smE + E_SSRC);
    int*   stgt = (int*)(smE + E_STGT);

    const int tid = threadIdx.x;
    const int lane = tid & 31, wid = tid >> 5;
    const int e0base = blockIdx.x * 128;
    const int is64 = g_is64;

    // load EF tile (fp32 -> bf16)
#pragma unroll
    for (int j = 0; j < 8; j++) {
        int id = j * 256 + tid;           // 2048 float4
        int row = id >> 4, seg = id & 15;
        float4 v = *(const float4*)(EF + ((size_t)(e0base + row)) * 64 + seg * 4);
        bf162 p0 = __floats2bfloat162_rn(v.x, v.y);
        bf162 p1 = __floats2bfloat162_rn(v.z, v.w);
        uint2 u; u.x = *(uint32_t*)&p0; u.y = *(uint32_t*)&p1;
        *(uint2*)(sEF + row * 72 + seg * 4) = u;
    }
    // load WeAT [256][64]
#pragma unroll
    for (int j = 0; j < 8; j++) {
        int id = j * 256 + tid;           // 2048 uint4 of halves? 256*64/8 = 2048
        int row = id >> 3, seg = id & 7;
        uint4 v = *(const uint4*)(g_WeATb + row * 64 + seg * 8);
        *(uint4*)(sWT + row * 72 + seg * 8) = v;
    }
    // A2T [8][256] -> [8][264]
    if (tid < 128) {
        int row = tid >> 4, seg = tid & 15;
        uint4 v = *(const uint4*)(g_A2Tb + row * 256 + seg * 16);
        *(uint4*)(sA2T + row * 264 + seg * 16) = v;
    }
    sc[tid] = g_cvec[tid];
    if (tid < 8) sa2[tid] = a2[tid];
    if (tid < 128) {
        ssrc[tid] = ld_idx(EI, e0base + tid, is64);
        stgt[tid] = ld_idx(EI, N_EDGES + e0base + tid, is64);
    }
    __syncthreads();

    // preload A fragments (EF tile rows = this warp's 16 edges)
    const int rA = wid * 16 + (lane >> 2);
    uint32_t Af[4][4];
#pragma unroll
    for (int kh = 0; kh < 4; kh++) {
        int off = rA * 72 + kh * 16 + (lane & 3) * 2;
        Af[kh][0] = *(const uint32_t*)(sEF + off);
        Af[kh][1] = *(const uint32_t*)(sEF + off + 8 * 72);
        Af[kh][2] = *(const uint32_t*)(sEF + off + 8);
        Af[kh][3] = *(const uint32_t*)(sEF + off + 8 * 72 + 8);
    }

    const int sn0 = ssrc[wid * 16 + (lane >> 2)];
    const int sn1 = ssrc[wid * 16 + (lane >> 2) + 8];
    const int tn0 = stgt[wid * 16 + (lane >> 2)];
    const int tn1 = stgt[wid * 16 + (lane >> 2) + 8];

    float hacc[4] = {0.f, 0.f, 0.f, 0.f};

#pragma unroll
    for (int half = 0; half < 2; half++) {
        float acc[16][4];
#pragma unroll
        for (int nt = 0; nt < 16; nt++)
#pragma unroll
            for (int c = 0; c < 4; c++) acc[nt][c] = 0.f;

#pragma unroll
        for (int kh = 0; kh < 4; kh++) {
            const int kc = kh * 16 + (lane & 3) * 2;
#pragma unroll
            for (int nt = 0; nt < 16; nt++) {
                int n = half * 128 + nt * 8 + (lane >> 2);
                uint32_t b0 = *(const uint32_t*)(sWT + n * 72 + kc);
                uint32_t b1 = *(const uint32_t*)(sWT + n * 72 + kc + 8);
                mma16816(acc[nt], Af[kh][0], Af[kh][1], Af[kh][2], Af[kh][3], b0, b1);
            }
        }

        // epilogue: z = lrelu(acc + q + k + c), pack to bf16 A-fragments
        uint32_t zbuf[8][4];
#pragma unroll
        for (int nt = 0; nt < 16; nt++) {
            int colbase = half * 128 + nt * 8 + (lane & 3) * 2;
            float cc0 = sc[colbase], cc1 = sc[colbase + 1];
            int tt = nt >> 1;
#pragma unroll
            for (int i = 0; i < 2; i++) {
                int sn = i ? sn1 : sn0;
                int tn = i ? tn1 : tn0;
                bf162 qp = *(const bf162*)(g_nodeqk + (size_t)sn * 512 + colbase);
                bf162 kp = *(const bf162*)(g_nodeqk + (size_t)tn * 512 + 256 + colbase);
                float z0 = lrelu(acc[nt][2 * i]     + __bfloat162float(qp.x) + __bfloat162float(kp.x) + cc0);
                float z1 = lrelu(acc[nt][2 * i + 1] + __bfloat162float(qp.y) + __bfloat162float(kp.y) + cc1);
                zbuf[tt][(nt & 1) * 2 + i] = pack_bf16(z0, z1);
            }
        }

        // scores mma: z @ A2 over this half's 128 dims
#pragma unroll
        for (int tt = 0; tt < 8; tt++) {
            int kcol = half * 128 + tt * 16 + (lane & 3) * 2;
            uint32_t b0 = *(const uint32_t*)(sA2T + (lane >> 2) * 264 + kcol);
            uint32_t b1 = *(const uint32_t*)(sA2T + (lane >> 2) * 264 + kcol + 8);
            mma16816(hacc, zbuf[tt][0], zbuf[tt][1], zbuf[tt][2], zbuf[tt][3], b0, b1);
        }
    }

    // heads: cols (lane%4)*2 + {0,1}; rows lane/4 (+8). lrelu+bias, mean over 8 heads.
    float a20 = sa2[(lane & 3) * 2], a21 = sa2[(lane & 3) * 2 + 1];
    float s0 = lrelu(hacc[0] + a20) + lrelu(hacc[1] + a21);
    float s1 = lrelu(hacc[2] + a20) + lrelu(hacc[3] + a21);
    s0 += __shfl_xor_sync(0xffffffffu, s0, 1);
    s0 += __shfl_xor_sync(0xffffffffu, s0, 2);
    s1 += __shfl_xor_sync(0xffffffffu, s1, 1);
    s1 += __shfl_xor_sync(0xffffffffu, s1, 2);
    if ((lane & 3) == 0) {
        int eg = e0base + wid * 16 + (lane >> 2);
        g_s[eg] = s0 * 0.125f;
        g_s[eg + 8] = s1 * 0.125f;
    }
}

// ---------------- softmax reductions ----------------
__device__ __forceinline__ unsigned f2u_ord(float f) {
    unsigned u = __float_as_uint(f);
    return (u & 0x80000000u) ? ~u : (u | 0x80000000u);
}
__device__ __forceinline__ float u2f_ord(unsigned u) {
    return (u & 0x80000000u) ? __uint_as_float(u ^ 0x80000000u) : __uint_as_float(~u);
}

__global__ void k_smax() {
    float m = -3.4e38f;
    for (int i = blockIdx.x * blockDim.x + threadIdx.x; i < N_EDGES; i += gridDim.x * blockDim.x)
        m = fmaxf(m, g_s[i]);
#pragma unroll
    for (int off = 16; off; off >>= 1) m = fmaxf(m, __shfl_xor_sync(0xffffffffu, m, off));
    __shared__ float sm[8];
    if ((threadIdx.x & 31) == 0) sm[threadIdx.x >> 5] = m;
    __syncthreads();
    if (threadIdx.x == 0) {
        for (int i = 1; i < 8; i++) m = fmaxf(m, sm[i]);
        atomicMax(&g_smax_u, f2u_ord(m));
    }
}

__global__ void k_ssum() {
    float mx = u2f_ord(g_smax_u);
    float s = 0.f;
    for (int i = blockIdx.x * blockDim.x + threadIdx.x; i < N_EDGES; i += gridDim.x * blockDim.x)
        s += expf(g_s[i] - mx);
#pragma unroll
    for (int off = 16; off; off >>= 1) s += __shfl_xor_sync(0xffffffffu, s, off);
    __shared__ float sm[8];
    if ((threadIdx.x & 31) == 0) sm[threadIdx.x >> 5] = s;
    __syncthreads();
    if (threadIdx.x == 0) {
        for (int i = 1; i < 8; i++) s += sm[i];
        atomicAdd(&g_ssum, s);
    }
}

// ---------------- counting sort by src ----------------
__global__ void k_hist(const void* __restrict__ EI) {
    int e = blockIdx.x * blockDim.x + threadIdx.x;
    int is64 = g_is64;
    if (e < N_EDGES) atomicAdd(&g_deg[ld_idx(EI, e, is64)], 1);
}

__global__ void k_scan() {
    int tid = threadIdx.x;
    int x[16];
    int base = tid * 16;
    int tot = 0;
#pragma unroll
    for (int i = 0; i < 16; i++) { x[i] = g_deg[base + i]; tot += x[i]; }
    int v = tot;
#pragma unroll
    for (int off = 1; off < 32; off <<= 1) {
        int t = __shfl_up_sync(0xffffffffu, v, off);
        if ((tid & 31) >= off) v += t;
    }
    __shared__ int sw[32];
    if ((tid & 31) == 31) sw[tid >> 5] = v;
    __syncthreads();
    if (tid < 32) {
        int t = sw[tid];
        int v2 = t;
#pragma unroll
        for (int off = 1; off < 32; off <<= 1) {
            int u = __shfl_up_sync(0xffffffffu, v2, off);
            if (tid >= off) v2 += u;
        }
        sw[tid] = v2 - t;
    }
    __syncthreads();
    int run = sw[tid >> 5] + v - tot;
#pragma unroll
    for (int i = 0; i < 16; i++) { g_off[base + i] = run; run += x[i]; }
    if (tid == 1023) g_off[N_NODES] = run;
}

__global__ void k_place(const void* __restrict__ EI) {
    int e = blockIdx.x * blockDim.x + threadIdx.x;
    int is64 = g_is64;
    if (e < N_EDGES) {
        int sn = ld_idx(EI, e, is64);
        int p = atomicAdd(&g_cur[sn], 1);
        g_eidx[g_off[sn] + p] = e;
    }
}

// ---------------- final: softmax weight + gather w*v[tgt], add h, LayerNorm --
__global__ void __launch_bounds__(256) k_final(const void* __restrict__ EI,
                                               const float* __restrict__ gamma,
                                               const float* __restrict__ beta,
                                               float* __restrict__ out) {
    int n = blockIdx.x;
    int d = threadIdx.x;
    int is64 = g_is64;
    float mx = u2f_ord(g_smax_u);
    float rinv = 1.f / g_ssum;
    float acc = g_node[n * 512 + d];  // h
    int beg = g_off[n], end = g_off[n + 1];

    __shared__ float swv[256];
    __shared__ int stg[256];
    for (int chunk = beg; chunk < end; chunk += 256) {
        int m = min(256, end - chunk);
        if (d < m) {
            int e = g_eidx[chunk + d];
            swv[d] = expf(g_s[e] - mx) * rinv;
            stg[d] = ld_idx(EI, N_EDGES + e, is64);
        }
        __syncthreads();
        for (int i = 0; i < m; i++)
            acc += swv[i] * g_node[stg[i] * 512 + 256 + d];  // v
        __syncthreads();
    }

    float v1 = acc, v2 = acc * acc;
#pragma unroll
    for (int off = 16; off; off >>= 1) {
        v1 += __shfl_xor_sync(0xffffffffu, v1, off);
        v2 += __shfl_xor_sync(0xffffffffu, v2, off);
    }
    __shared__ float s1[8], s2[8];
    __shared__ float s_mu, s_rstd;
    int wid = d >> 5, lane = d & 31;
    if (lane == 0) { s1[wid] = v1; s2[wid] = v2; }
    __syncthreads();
    if (d == 0) {
        float S = 0.f, Q = 0.f;
        for (int i = 0; i < 8; i++) { S += s1[i]; Q += s2[i]; }
        float mu = S * (1.f / 256.f);
        float var = Q * (1.f / 256.f) - mu * mu;
        s_mu = mu;
        s_rstd = rsqrtf(var + 1e-5f);
    }
    __syncthreads();
    out[n * 256 + d] = (acc - s_mu) * s_rstd * gamma[d] + beta[d];
}

// ---------------- launch ----------------
extern "C" void kernel_launch(void* const* d_in, const int* in_sizes, int n_in,
                              void* d_out, int out_size) {
    const float* X     = (const float*)d_in[0];
    const void*  EI    = d_in[1];
    const float* EF    = (const float*)d_in[2];
    const float* Wn    = (const float*)d_in[3];
    const float* bn    = (const float*)d_in[4];
    const float* Wq    = (const float*)d_in[5];
    const float* bq    = (const float*)d_in[6];
    const float* Wk    = (const float*)d_in[7];
    const float* bk    = (const float*)d_in[8];
    const float* Wv    = (const float*)d_in[9];
    const float* bv    = (const float*)d_in[10];
    const float* We    = (const float*)d_in[11];
    const float* be    = (const float*)d_in[12];
    const float* A1    = (const float*)d_in[13];
    const float* a1    = (const float*)d_in[14];
    const float* A2    = (const float*)d_in[15];
    const float* a2    = (const float*)d_in[16];
    const float* gamma = (const float*)d_in[17];
    const float* beta  = (const float*)d_in[18];
    float* out = (float*)d_out;

    cudaFuncSetAttribute(k_node_gemm, cudaFuncAttributeMaxDynamicSharedMemorySize, NGM_SMEM);
    cudaFuncSetAttribute(k_edge, cudaFuncAttributeMaxDynamicSharedMemorySize, EDGE_SMEM);

    k_detect<<<1, 256>>>(EI);
    k_init<<<64, 256>>>();
    k_prep_copy<<<512, 256>>>(Wn, bn, Wv, bv);
    k_prep_fold<<<579, 256>>>(Wq, bq, Wk, bk, We, be, A1, a1);
    k_convX<<<16384, 256>>>(X);
    k_convW<<<1096, 256>>>(A2);
    k_node_gemm<<<dim3(8, 128), 256, NGM_SMEM>>>();
    k_edge<<<2048, 256, EDGE_SMEM>>>(EF, EI, a2);
    k_smax<<<256, 256>>>();
    k_ssum<<<256, 256>>>();
    k_hist<<<1024, 256>>>(EI);
    k_scan<<<1, 1024>>>();
    k_place<<<1024, 256>>>(EI);
    k_final<<<16384, 256>>>(EI, gamma, beta, out);
}

// round 6
// speedup vs baseline: 2.4212x; 1.0408x over previous
#include <cuda_runtime.h>
#include <cuda_bf16.h>
#include <math.h>
#include <stdint.h>

#define N_NODES 16384
#define N_EDGES 262144
#define DN 256
#define DE 64
#define NH 8

typedef __nv_bfloat16 bf16;
typedef __nv_bfloat162 bf162;

// ---------------- device scratch (static allocations only) ----------------
__device__ bf16  g_WThi[1024 * 256];           // W^T [n][k]: Wn|Wv|WqA1q|WkA1k (hi)
__device__ bf16  g_WTlo[1024 * 256];           // lo (only n<512 written/used)
__device__ float g_bbig[512];                  // bn | bv
__device__ bf16  g_Xhi[N_NODES * 256];
__device__ bf16  g_Xlo[N_NODES * 256];
__device__ bf16  g_WeATb[256 * 64];            // (We@A1e)^T [n=256][k=64] bf16
__device__ float g_cvec[DN];                   // bq@A1q + bk@A1k + be@A1e + a1
__device__ bf16  g_A2Tb[8 * 256];              // A2^T [h][d] bf16
__device__ float g_h[N_NODES * 256];           // h (fp32)
__device__ bf16  g_vb[N_NODES * 256];          // v (bf16)
__device__ bf16  g_nodeqk[N_NODES * 512];      // Pq | Pk (bf16)
__device__ float g_s[N_EDGES];                 // per-edge pre-softmax score
__device__ int   g_deg[N_NODES];
__device__ int   g_off[N_NODES + 1];
__device__ int   g_cur[N_NODES];
__device__ int   g_eidx[N_EDGES];
__device__ unsigned int g_smax_u;
__device__ float g_ssum;
__device__ int   g_is64;

__device__ __forceinline__ float lrelu(float x) { return x > 0.f ? x : 0.2f * x; }

__device__ __forceinline__ int ld_idx(const void* EI, int pos, int is64) {
    if (is64) return (int)((const long long*)EI)[pos];
    return ((const int*)EI)[pos];
}

__device__ __forceinline__ uint32_t pack_bf16(float x, float y) {
    bf162 p = __floats2bfloat162_rn(x, y);
    return *reinterpret_cast<uint32_t*>(&p);
}

__device__ __forceinline__ void mma16816(float* d, uint32_t a0, uint32_t a1, uint32_t a2, uint32_t a3,
                                         uint32_t b0, uint32_t b1) {
    asm volatile(
        "mma.sync.aligned.m16n8k16.row.col.f32.bf16.bf16.f32 "
        "{%0,%1,%2,%3},{%4,%5,%6,%7},{%8,%9},{%0,%1,%2,%3};"
        : "+f"(d[0]), "+f"(d[1]), "+f"(d[2]), "+f"(d[3])
        : "r"(a0), "r"(a1), "r"(a2), "r"(a3), "r"(b0), "r"(b1));
}

__device__ __forceinline__ uint32_t smem_u32(const void* p) {
    return (uint32_t)__cvta_generic_to_shared(p);
}
#define CP16(dst, src) asm volatile("cp.async.ca.shared.global [%0], [%1], 16;\n" :: "r"(dst), "l"(src))

__device__ __forceinline__ unsigned f2u_ord(float f) {
    unsigned u = __float_as_uint(f);
    return (u & 0x80000000u) ? ~u : (u | 0x80000000u);
}
__device__ __forceinline__ float u2f_ord(unsigned u) {
    return (u & 0x80000000u) ? __uint_as_float(u ^ 0x80000000u) : __uint_as_float(~u);
}

// ---------------- k_pre: detect dtype, init counters, Wn/Wv transpose-split, A2T --
__global__ void k_pre(const void* EI, const float* __restrict__ Wn, const float* __restrict__ bn,
                      const float* __restrict__ Wv, const float* __restrict__ bv,
                      const float* __restrict__ A2) {
    int gtid = blockIdx.x * blockDim.x + threadIdx.x;   // 512*256 = 131072
    if (blockIdx.x == 0) {
        __shared__ int bad;
        if (threadIdx.x == 0) bad = 0;
        __syncthreads();
        long long v = ((const long long*)EI)[threadIdx.x];
        if (v < 0 || v >= N_NODES) atomicOr(&bad, 1);
        __syncthreads();
        if (threadIdx.x == 0) g_is64 = bad ? 0 : 1;
    }
    {   // Wn|Wv -> transposed hi/lo  (k row, j col of 512)
        int k = gtid >> 9, j = gtid & 511;
        float w = (j < 256) ? Wn[k * 256 + j] : Wv[k * 256 + j - 256];
        bf16 hi = __float2bfloat16_rn(w);
        g_WThi[j * 256 + k] = hi;
        g_WTlo[j * 256 + k] = __float2bfloat16_rn(w - __bfloat162float(hi));
    }
    if (gtid < N_NODES) { g_deg[gtid] = 0; g_cur[gtid] = 0; }
    if (gtid < 512) g_bbig[gtid] = (gtid < 256) ? bn[gtid] : bv[gtid - 256];
    if (gtid < 2048) { int h = gtid >> 8, d = gtid & 255; g_A2Tb[gtid] = __float2bfloat16_rn(A2[d * 8 + h]); }
    if (gtid == 0) { g_smax_u = 0u; g_ssum = 0.f; }
}

// ---------------- k_prep_fold: tiled GEMMs WqA/WkA/WeA + cvec --------------
// blocks 0-63: WqA, 64-127: WkA, 128-143: WeA, 144: cvec. 32x32 tiles.
__global__ void __launch_bounds__(256) k_prep_fold(const float* __restrict__ Wq, const float* __restrict__ bq,
                                                   const float* __restrict__ Wk, const float* __restrict__ bk,
                                                   const float* __restrict__ We, const float* __restrict__ be,
                                                   const float* __restrict__ A1, const float* __restrict__ a1) {
    int bid = blockIdx.x;
    int tid = threadIdx.x;
    if (bid == 144) {   // cvec
        int j = tid;
        float s = a1[j];
#pragma unroll 4
        for (int m = 0; m < 256; m++) {
            s += bq[m] * A1[m * 256 + j];
            s += bk[m] * A1[(256 + m) * 256 + j];
            s += be[m] * A1[(512 + m) * 256 + j];
        }
        g_cvec[j] = s;
        return;
    }
    int z, kt, jt, zoff;
    const float* W;
    if (bid < 64)       { z = 0; W = Wq; zoff = 0;   int t = bid;       kt = t >> 3; jt = t & 7; }
    else if (bid < 128) { z = 1; W = Wk; zoff = 256; int t = bid - 64;  kt = t >> 3; jt = t & 7; }
    else                { z = 2; W = We; zoff = 512; int t = bid - 128; kt = t >> 3; jt = t & 7; }
    int k0 = kt * 32, j0 = jt * 32;
    __shared__ float Ws[32][33], As[32][33];
    int ty = tid >> 4, tx = tid & 15;
    float acc[2][2] = {{0.f, 0.f}, {0.f, 0.f}};
    for (int m0 = 0; m0 < 256; m0 += 32) {
#pragma unroll
        for (int i = 0; i < 4; i++) {
            int id = i * 256 + tid;
            int r = id >> 5, c = id & 31;
            Ws[r][c] = W[(k0 + r) * 256 + m0 + c];
            As[r][c] = A1[(zoff + m0 + r) * 256 + j0 + c];
        }
        __syncthreads();
#pragma unroll 8
        for (int m = 0; m < 32; m++) {
            float a0 = Ws[ty * 2][m], a1v = Ws[ty * 2 + 1][m];
            float b0 = As[m][tx * 2], b1 = As[m][tx * 2 + 1];
            acc[0][0] += a0 * b0; acc[0][1] += a0 * b1;
            acc[1][0] += a1v * b0; acc[1][1] += a1v * b1;
        }
        __syncthreads();
    }
#pragma unroll
    for (int i = 0; i < 2; i++)
#pragma unroll
        for (int j = 0; j < 2; j++) {
            int k = k0 + ty * 2 + i, jg = j0 + tx * 2 + j;
            if (z < 2) g_WThi[(512 + z * 256 + jg) * 256 + k] = __float2bfloat16_rn(acc[i][j]);
            else       g_WeATb[jg * 64 + k] = __float2bfloat16_rn(acc[i][j]);
        }
}

// ---------------- k_convX: X -> hi/lo bf16 (float4 vectorized) -------------
__global__ void k_convX(const float* __restrict__ X) {
    int i = blockIdx.x * blockDim.x + threadIdx.x;   // over 1M float4s
    float4 v = ((const float4*)X)[i];
    bf162 h0 = __floats2bfloat162_rn(v.x, v.y);
    bf162 h1 = __floats2bfloat162_rn(v.z, v.w);
    bf162 l0 = __floats2bfloat162_rn(v.x - __bfloat162float(h0.x), v.y - __bfloat162float(h0.y));
    bf162 l1 = __floats2bfloat162_rn(v.z - __bfloat162float(h1.x), v.w - __bfloat162float(h1.y));
    uint2 uh, ul;
    uh.x = *(uint32_t*)&h0; uh.y = *(uint32_t*)&h1;
    ul.x = *(uint32_t*)&l0; ul.y = *(uint32_t*)&l1;
    ((uint2*)g_Xhi)[i] = uh;
    ((uint2*)g_Xlo)[i] = ul;
}

// ---------------- node GEMM: [16384,256] @ [256,1024] ----------------------
// bx<2 (h): 3-pass split bf16 -> fp32.  bx 2,3 (v): 1-pass -> bf16.
// bx>=4 (Pq|Pk): 1-pass -> bf16.  8 warps (4m x 2n), warp tile 32x64.
#define NGM_SMEM (2 * 4 * 128 * 40 * 2)   // 81920 bytes

__global__ void __launch_bounds__(256) k_node_gemm() {
    extern __shared__ bf16 smN[];
    const int tid = threadIdx.x;
    const int lane = tid & 31, wid = tid >> 5;
    const int wm = wid & 3, wn = wid >> 2;
    const int bx = blockIdx.x;
    const int m0 = blockIdx.y * 128, n0 = bx * 128;
    const bool full3 = (bx < 2);

    float acc[2][8][4];
#pragma unroll
    for (int mt = 0; mt < 2; mt++)
#pragma unroll
        for (int nt = 0; nt < 8; nt++)
#pragma unroll
            for (int c = 0; c < 4; c++) acc[mt][nt][c] = 0.f;

    auto load_chunk = [&](int c, int buf) {
        int k0 = c * 32;
        if (full3) {
#pragma unroll
            for (int j = 0; j < 8; j++) {
                int id = j * 256 + tid;
                int arr = id >> 9;
                int rem = id & 511;
                int row = rem >> 2, seg = rem & 3;
                const bf16* src;
                if (arr == 0)      src = g_Xhi  + (m0 + row) * 256 + k0 + seg * 8;
                else if (arr == 1) src = g_Xlo  + (m0 + row) * 256 + k0 + seg * 8;
                else if (arr == 2) src = g_WThi + (n0 + row) * 256 + k0 + seg * 8;
                else               src = g_WTlo + (n0 + row) * 256 + k0 + seg * 8;
                uint32_t dst = smem_u32(smN + buf * 20480 + arr * 5120 + row * 40 + seg * 8);
                CP16(dst, src);
            }
        } else {
#pragma unroll
            for (int j = 0; j < 4; j++) {
                int id = j * 256 + tid;
                int sel = id >> 9;
                int rem = id & 511;
                int row = rem >> 2, seg = rem & 3;
                const bf16* src = (sel == 0) ? g_Xhi + (m0 + row) * 256 + k0 + seg * 8
                                             : g_WThi + (n0 + row) * 256 + k0 + seg * 8;
                uint32_t dst = smem_u32(smN + buf * 20480 + (sel * 2) * 5120 + row * 40 + seg * 8);
                CP16(dst, src);
            }
        }
        asm volatile("cp.async.commit_group;\n" ::);
    };

    load_chunk(0, 0);

    for (int c = 0; c < 8; c++) {
        if (c < 7) load_chunk(c + 1, (c + 1) & 1);
        if (c < 7) asm volatile("cp.async.wait_group 1;\n" ::);
        else       asm volatile("cp.async.wait_group 0;\n" ::);
        __syncthreads();

        const int bb = (c & 1) * 20480;
        const bf16* sAh = smN + bb;
        const bf16* sAl = smN + bb + 5120;
        const bf16* sBh = smN + bb + 2 * 5120;
        const bf16* sBl = smN + bb + 3 * 5120;

#pragma unroll
        for (int kh = 0; kh < 2; kh++) {
            const int kc = kh * 16 + (lane & 3) * 2;
            uint32_t Ah[2][4], Bh[8][2];
#pragma unroll
            for (int mt = 0; mt < 2; mt++) {
                int r = wm * 32 + mt * 16 + (lane >> 2);
                Ah[mt][0] = *(const uint32_t*)(sAh + r * 40 + kc);
                Ah[mt][1] = *(const uint32_t*)(sAh + (r + 8) * 40 + kc);
                Ah[mt][2] = *(const uint32_t*)(sAh + r * 40 + kc + 8);
                Ah[mt][3] = *(const uint32_t*)(sAh + (r + 8) * 40 + kc + 8);
            }
#pragma unroll
            for (int nt = 0; nt < 8; nt++) {
                int n = wn * 64 + nt * 8 + (lane >> 2);
                Bh[nt][0] = *(const uint32_t*)(sBh + n * 40 + kc);
                Bh[nt][1] = *(const uint32_t*)(sBh + n * 40 + kc + 8);
            }
            if (full3) {
                uint32_t Al[2][4], Bl[8][2];
#pragma unroll
                for (int mt = 0; mt < 2; mt++) {
                    int r = wm * 32 + mt * 16 + (lane >> 2);
                    Al[mt][0] = *(const uint32_t*)(sAl + r * 40 + kc);
                    Al[mt][1] = *(const uint32_t*)(sAl + (r + 8) * 40 + kc);
                    Al[mt][2] = *(const uint32_t*)(sAl + r * 40 + kc + 8);
                    Al[mt][3] = *(const uint32_t*)(sAl + (r + 8) * 40 + kc + 8);
                }
#pragma unroll
                for (int nt = 0; nt < 8; nt++) {
                    int n = wn * 64 + nt * 8 + (lane >> 2);
                    Bl[nt][0] = *(const uint32_t*)(sBl + n * 40 + kc);
                    Bl[nt][1] = *(const uint32_t*)(sBl + n * 40 + kc + 8);
                }
#pragma unroll
                for (int mt = 0; mt < 2; mt++)
#pragma unroll
                    for (int nt = 0; nt < 8; nt++) {
                        mma16816(acc[mt][nt], Ah[mt][0], Ah[mt][1], Ah[mt][2], Ah[mt][3], Bh[nt][0], Bh[nt][1]);
                        mma16816(acc[mt][nt], Ah[mt][0], Ah[mt][1], Ah[mt][2], Ah[mt][3], Bl[nt][0], Bl[nt][1]);
                        mma16816(acc[mt][nt], Al[mt][0], Al[mt][1], Al[mt][2], Al[mt][3], Bh[nt][0], Bh[nt][1]);
                    }
            } else {
#pragma unroll
                for (int mt = 0; mt < 2; mt++)
#pragma unroll
                    for (int nt = 0; nt < 8; nt++)
                        mma16816(acc[mt][nt], Ah[mt][0], Ah[mt][1], Ah[mt][2], Ah[mt][3], Bh[nt][0], Bh[nt][1]);
            }
        }
        __syncthreads();
    }

#pragma unroll
    for (int mt = 0; mt < 2; mt++) {
        int r0 = m0 + wm * 32 + mt * 16 + (lane >> 2);
#pragma unroll
        for (int nt = 0; nt < 8; nt++) {
            int colg = n0 + wn * 64 + nt * 8 + (lane & 3) * 2;
            if (bx < 2) {
                float b0 = g_bbig[colg], b1 = g_bbig[colg + 1];
                *(float2*)(g_h + r0 * 256 + colg) = make_float2(acc[mt][nt][0] + b0, acc[mt][nt][1] + b1);
                *(float2*)(g_h + (r0 + 8) * 256 + colg) = make_float2(acc[mt][nt][2] + b0, acc[mt][nt][3] + b1);
            } else if (bx < 4) {
                float b0 = g_bbig[colg], b1 = g_bbig[colg + 1];
                int cc = colg - 256;
                *(bf162*)(g_vb + r0 * 256 + cc) = __floats2bfloat162_rn(acc[mt][nt][0] + b0, acc[mt][nt][1] + b1);
                *(bf162*)(g_vb + (r0 + 8) * 256 + cc) = __floats2bfloat162_rn(acc[mt][nt][2] + b0, acc[mt][nt][3] + b1);
            } else {
                int cc = colg - 512;
                *(bf162*)(g_nodeqk + r0 * 512 + cc) = __floats2bfloat162_rn(acc[mt][nt][0], acc[mt][nt][1]);
                *(bf162*)(g_nodeqk + (r0 + 8) * 512 + cc) = __floats2bfloat162_rn(acc[mt][nt][2], acc[mt][nt][3]);
            }
        }
    }
}

// ---------------- fused edge kernel (tensor cores + max + hist) ------------
#define E_SEF   0
#define E_SWT   18432
#define E_SA2T  55296
#define E_SC    59520
#define E_SA2   60544
#define E_SSRC  60576
#define E_STGT  61088
#define EDGE_SMEM 61600

__global__ void __launch_bounds__(256) k_edge(const float* __restrict__ EF,
                                              const void* __restrict__ EI,
                                              const float* __restrict__ a2) {
    extern __shared__ char smE[];
    bf16*  sEF  = (bf16*)(smE + E_SEF);     // [128][72]
    bf16*  sWT  = (bf16*)(smE + E_SWT);     // [256][72]
    bf16*  sA2T = (bf16*)(smE + E_SA2T);    // [8][264]
    float* sc   = (float*)(smE + E_SC);
    float* sa2  = (float*)(smE + E_SA2);
    int*   ssrc = (int*)(smE + E_SSRC);
    int*   stgt = (int*)(smE + E_STGT);

    const int tid = threadIdx.x;
    const int lane = tid & 31, wid = tid >> 5;
    const int e0base = blockIdx.x * 128;
    const int is64 = g_is64;

#pragma unroll
    for (int j = 0; j < 8; j++) {
        int id = j * 256 + tid;
        int row = id >> 4, seg = id & 15;
        float4 v = *(const float4*)(EF + ((size_t)(e0base + row)) * 64 + seg * 4);
        bf162 p0 = __floats2bfloat162_rn(v.x, v.y);
        bf162 p1 = __floats2bfloat162_rn(v.z, v.w);
        uint2 u; u.x = *(uint32_t*)&p0; u.y = *(uint32_t*)&p1;
        *(uint2*)(sEF + row * 72 + seg * 4) = u;
    }
#pragma unroll
    for (int j = 0; j < 8; j++) {
        int id = j * 256 + tid;
        int row = id >> 3, seg = id & 7;
        uint4 v = *(const uint4*)(g_WeATb + row * 64 + seg * 8);
        *(uint4*)(sWT + row * 72 + seg * 8) = v;
    }
    {   // A2T: FULL coverage — 256 threads x 8 elements = 2048 (fix for the
        // half-coverage bug: previously 128 threads at stride 16 loaded only
        // 1024 of 2048 elements, leaving stale smem in the z@A2 operand)
        int row = tid >> 5, seg = tid & 31;
        uint4 v = *(const uint4*)(g_A2Tb + row * 256 + seg * 8);
        *(uint4*)(sA2T + row * 264 + seg * 8) = v;
    }
    sc[tid] = g_cvec[tid];
    if (tid < 8) sa2[tid] = a2[tid];
    if (tid < 128) {
        int sn = ld_idx(EI, e0base + tid, is64);
        ssrc[tid] = sn;
        stgt[tid] = ld_idx(EI, N_EDGES + e0base + tid, is64);
        atomicAdd(&g_deg[sn], 1);        // fused histogram
    }
    __syncthreads();

    const int rA = wid * 16 + (lane >> 2);
    uint32_t Af[4][4];
#pragma unroll
    for (int kh = 0; kh < 4; kh++) {
        int off = rA * 72 + kh * 16 + (lane & 3) * 2;
        Af[kh][0] = *(const uint32_t*)(sEF + off);
        Af[kh][1] = *(const uint32_t*)(sEF + off + 8 * 72);
        Af[kh][2] = *(const uint32_t*)(sEF + off + 8);
        Af[kh][3] = *(const uint32_t*)(sEF + off + 8 * 72 + 8);
    }

    const int sn0 = ssrc[wid * 16 + (lane >> 2)];
    const int sn1 = ssrc[wid * 16 + (lane >> 2) + 8];
    const int tn0 = stgt[wid * 16 + (lane >> 2)];
    const int tn1 = stgt[wid * 16 + (lane >> 2) + 8];

    float hacc[4] = {0.f, 0.f, 0.f, 0.f};

#pragma unroll
    for (int half = 0; half < 2; half++) {
        float acc[16][4];
#pragma unroll
        for (int nt = 0; nt < 16; nt++)
#pragma unroll
            for (int c = 0; c < 4; c++) acc[nt][c] = 0.f;

#pragma unroll
        for (int kh = 0; kh < 4; kh++) {
            const int kc = kh * 16 + (lane & 3) * 2;
#pragma unroll
            for (int nt = 0; nt < 16; nt++) {
                int n = half * 128 + nt * 8 + (lane >> 2);
                uint32_t b0 = *(const uint32_t*)(sWT + n * 72 + kc);
                uint32_t b1 = *(const uint32_t*)(sWT + n * 72 + kc + 8);
                mma16816(acc[nt], Af[kh][0], Af[kh][1], Af[kh][2], Af[kh][3], b0, b1);
            }
        }

        uint32_t zbuf[8][4];
#pragma unroll
        for (int nt = 0; nt < 16; nt++) {
            int colbase = half * 128 + nt * 8 + (lane & 3) * 2;
            float cc0 = sc[colbase], cc1 = sc[colbase + 1];
            int tt = nt >> 1;
#pragma unroll
            for (int i = 0; i < 2; i++) {
                int sn = i ? sn1 : sn0;
                int tn = i ? tn1 : tn0;
                bf162 qp = *(const bf162*)(g_nodeqk + (size_t)sn * 512 + colbase);
                bf162 kp = *(const bf162*)(g_nodeqk + (size_t)tn * 512 + 256 + colbase);
                float z0 = lrelu(acc[nt][2 * i]     + __bfloat162float(qp.x) + __bfloat162float(kp.x) + cc0);
                float z1 = lrelu(acc[nt][2 * i + 1] + __bfloat162float(qp.y) + __bfloat162float(kp.y) + cc1);
                zbuf[tt][(nt & 1) * 2 + i] = pack_bf16(z0, z1);
            }
        }

#pragma unroll
        for (int tt = 0; tt < 8; tt++) {
            int kcol = half * 128 + tt * 16 + (lane & 3) * 2;
            uint32_t b0 = *(const uint32_t*)(sA2T + (lane >> 2) * 264 + kcol);
            uint32_t b1 = *(const uint32_t*)(sA2T + (lane >> 2) * 264 + kcol + 8);
            mma16816(hacc, zbuf[tt][0], zbuf[tt][1], zbuf[tt][2], zbuf[tt][3], b0, b1);
        }
    }

    float a20 = sa2[(lane & 3) * 2], a21 = sa2[(lane & 3) * 2 + 1];
    float s0 = lrelu(hacc[0] + a20) + lrelu(hacc[1] + a21);
    float s1 = lrelu(hacc[2] + a20) + lrelu(hacc[3] + a21);
    s0 += __shfl_xor_sync(0xffffffffu, s0, 1);
    s0 += __shfl_xor_sync(0xffffffffu, s0, 2);
    s1 += __shfl_xor_sync(0xffffffffu, s1, 1);
    s1 += __shfl_xor_sync(0xffffffffu, s1, 2);
    if ((lane & 3) == 0) {
        int eg = e0base + wid * 16 + (lane >> 2);
        g_s[eg] = s0 * 0.125f;
        g_s[eg + 8] = s1 * 0.125f;
    }
    // fused block max -> atomicMax
    float mval = fmaxf(s0, s1) * 0.125f;
#pragma unroll
    for (int off = 4; off < 32; off <<= 1)
        mval = fmaxf(mval, __shfl_xor_sync(0xffffffffu, mval, off));
    __shared__ float swm[8];
    if (lane == 0) swm[wid] = mval;
    __syncthreads();
    if (tid == 0) {
        float m = swm[0];
#pragma unroll
        for (int i = 1; i < 8; i++) m = fmaxf(m, swm[i]);
        atomicMax(&g_smax_u, f2u_ord(m));
    }
}

// ---------------- counting sort scan ----------------
__global__ void k_scan() {
    int tid = threadIdx.x;
    int x[16];
    int base = tid * 16;
    int tot = 0;
#pragma unroll
    for (int i = 0; i < 16; i++) { x[i] = g_deg[base + i]; tot += x[i]; }
    int v = tot;
#pragma unroll
    for (int off = 1; off < 32; off <<= 1) {
        int t = __shfl_up_sync(0xffffffffu, v, off);
        if ((tid & 31) >= off) v += t;
    }
    __shared__ int sw[32];
    if ((tid & 31) == 31) sw[tid >> 5] = v;
    __syncthreads();
    if (tid < 32) {
        int t = sw[tid];
        int v2 = t;
#pragma unroll
        for (int off = 1; off < 32; off <<= 1) {
            int u = __shfl_up_sync(0xffffffffu, v2, off);
            if (tid >= off) v2 += u;
        }
        sw[tid] = v2 - t;
    }
    __syncthreads();
    int run = sw[tid >> 5] + v - tot;
#pragma unroll
    for (int i = 0; i < 16; i++) { g_off[base + i] = run; run += x[i]; }
    if (tid == 1023) g_off[N_NODES] = run;
}

// ---------------- place + exp-sum fused ----------------
__global__ void k_place_ssum(const void* __restrict__ EI) {
    int e = blockIdx.x * blockDim.x + threadIdx.x;
    int is64 = g_is64;
    float mx = u2f_ord(g_smax_u);
    float s = 0.f;
    if (e < N_EDGES) {
        int sn = ld_idx(EI, e, is64);
        int p = atomicAdd(&g_cur[sn], 1);
        g_eidx[g_off[sn] + p] = e;
        s = expf(g_s[e] - mx);
    }
#pragma unroll
    for (int off = 16; off; off >>= 1) s += __shfl_xor_sync(0xffffffffu, s, off);
    __shared__ float sm[8];
    if ((threadIdx.x & 31) == 0) sm[threadIdx.x >> 5] = s;
    __syncthreads();
    if (threadIdx.x == 0) {
        for (int i = 1; i < 8; i++) s += sm[i];
        atomicAdd(&g_ssum, s);
    }
}

// ---------------- final: weights + gather w*v[tgt] (bf16), add h, LayerNorm --
__global__ void __launch_bounds__(256) k_final(const void* __restrict__ EI,
                                               const float* __restrict__ gamma,
                                               const float* __restrict__ beta,
                                               float* __restrict__ out) {
    int n = blockIdx.x;
    int d = threadIdx.x;
    int is64 = g_is64;
    float mx = u2f_ord(g_smax_u);
    float rinv = 1.f / g_ssum;
    float acc = g_h[n * 256 + d];
    int beg = g_off[n], end = g_off[n + 1];

    __shared__ float swv[256];
    __shared__ int stg[256];
    for (int chunk = beg; chunk < end; chunk += 256) {
        int m = min(256, end - chunk);
        if (d < m) {
            int e = g_eidx[chunk + d];
            swv[d] = expf(g_s[e] - mx) * rinv;
            stg[d] = ld_idx(EI, N_EDGES + e, is64);
        }
        __syncthreads();
        for (int i = 0; i < m; i++)
            acc += swv[i] * __bfloat162float(g_vb[(size_t)stg[i] * 256 + d]);
        __syncthreads();
    }

    float v1 = acc, v2 = acc * acc;
#pragma unroll
    for (int off = 16; off; off >>= 1) {
        v1 += __shfl_xor_sync(0xffffffffu, v1, off);
        v2 += __shfl_xor_sync(0xffffffffu, v2, off);
    }
    __shared__ float s1[8], s2[8];
    __shared__ float s_mu, s_rstd;
    int wid = d >> 5, lane = d & 31;
    if (lane == 0) { s1[wid] = v1; s2[wid] = v2; }
    __syncthreads();
    if (d == 0) {
        float S = 0.f, Q = 0.f;
        for (int i = 0; i < 8; i++) { S += s1[i]; Q += s2[i]; }
        float mu = S * (1.f / 256.f);
        float var = Q * (1.f / 256.f) - mu * mu;
        s_mu = mu;
        s_rstd = rsqrtf(var + 1e-5f);
    }
    __syncthreads();
    out[n * 256 + d] = (acc - s_mu) * s_rstd * gamma[d] + beta[d];
}

// ---------------- launch ----------------
extern "C" void kernel_launch(void* const* d_in, const int* in_sizes, int n_in,
                              void* d_out, int out_size) {
    const float* X     = (const float*)d_in[0];
    const void*  EI    = d_in[1];
    const float* EF    = (const float*)d_in[2];
    const float* Wn    = (const float*)d_in[3];
    const float* bn    = (const float*)d_in[4];
    const float* Wq    = (const float*)d_in[5];
    const float* bq    = (const float*)d_in[6];
    const float* Wk    = (const float*)d_in[7];
    const float* bk    = (const float*)d_in[8];
    const float* Wv    = (const float*)d_in[9];
    const float* bv    = (const float*)d_in[10];
    const float* We    = (const float*)d_in[11];
    const float* be    = (const float*)d_in[12];
    const float* A1    = (const float*)d_in[13];
    const float* a1    = (const float*)d_in[14];
    const float* A2    = (const float*)d_in[15];
    const float* a2    = (const float*)d_in[16];
    const float* gamma = (const float*)d_in[17];
    const float* beta  = (const float*)d_in[18];
    float* out = (float*)d_out;

    cudaFuncSetAttribute(k_node_gemm, cudaFuncAttributeMaxDynamicSharedMemorySize, NGM_SMEM);
    cudaFuncSetAttribute(k_edge, cudaFuncAttributeMaxDynamicSharedMemorySize, EDGE_SMEM);

    k_pre<<<512, 256>>>(EI, Wn, bn, Wv, bv, A2);
    k_prep_fold<<<145, 256>>>(Wq, bq, Wk, bk, We, be, A1, a1);
    k_convX<<<4096, 256>>>(X);
    k_node_gemm<<<dim3(8, 128), 256, NGM_SMEM>>>();
    k_edge<<<2048, 256, EDGE_SMEM>>>(EF, EI, a2);
    k_scan<<<1, 1024>>>();
    k_place_ssum<<<1024, 256>>>(EI);
    k_final<<<16384, 256>>>(EI, gamma, beta, out);
}

// round 8
// speedup vs baseline: 2.5912x; 1.0702x over previous
#include <cuda_runtime.h>
#include <cuda_bf16.h>
#include <math.h>
#include <stdint.h>

#define N_NODES 16384
#define N_EDGES 262144
#define DN 256
#define DE 64
#define NH 8

typedef __nv_bfloat16 bf16;
typedef __nv_bfloat162 bf162;

// ---------------- device scratch (static allocations only) ----------------
__device__ bf16  g_WThi[1024 * 256];           // W^T [n][k]: Wn|Wv|WqA1q|WkA1k (hi)
__device__ bf16  g_WTlo[1024 * 256];           // lo (only n<512 written/used)
__device__ float g_bbig[512];                  // bn | bv
__device__ bf16  g_Xhi[N_NODES * 256];
__device__ bf16  g_Xlo[N_NODES * 256];
__device__ bf16  g_WeATb[256 * 64];            // (We@A1e)^T [n=256][k=64] bf16
__device__ float g_cvec[DN];                   // bq@A1q + bk@A1k + be@A1e + a1
__device__ bf16  g_A2Tb[8 * 256];              // A2^T [h][d] bf16
__device__ float g_h[N_NODES * 256];           // h (fp32)
__device__ bf16  g_vb[N_NODES * 256];          // v (bf16)
// Pq|Pk per node, PAIR-GROUPED layout: [node][arr(q=0,k=1)][j=0..3][p=0..31]
// where original col = p*8 + 2j (+1). 512 bf16 per node.
__device__ bf16  g_nodeqk[N_NODES * 512];
__device__ float g_s[N_EDGES];                 // per-edge pre-softmax score
__device__ int   g_deg[N_NODES];
__device__ int   g_off[N_NODES + 1];
__device__ int   g_cur[N_NODES];
__device__ int   g_eidx[N_EDGES];
__device__ unsigned int g_smax_u;
__device__ float g_ssum;
__device__ int   g_is64;

__device__ __forceinline__ float lrelu(float x) { return x > 0.f ? x : 0.2f * x; }

__device__ __forceinline__ int ld_idx(const void* EI, int pos, int is64) {
    if (is64) return (int)((const long long*)EI)[pos];
    return ((const int*)EI)[pos];
}

__device__ __forceinline__ uint32_t pack_bf16(float x, float y) {
    bf162 p = __floats2bfloat162_rn(x, y);
    return *reinterpret_cast<uint32_t*>(&p);
}

__device__ __forceinline__ void mma16816(float* d, uint32_t a0, uint32_t a1, uint32_t a2, uint32_t a3,
                                         uint32_t b0, uint32_t b1) {
    asm volatile(
        "mma.sync.aligned.m16n8k16.row.col.f32.bf16.bf16.f32 "
        "{%0,%1,%2,%3},{%4,%5,%6,%7},{%8,%9},{%0,%1,%2,%3};"
        : "+f"(d[0]), "+f"(d[1]), "+f"(d[2]), "+f"(d[3])
        : "r"(a0), "r"(a1), "r"(a2), "r"(a3), "r"(b0), "r"(b1));
}

__device__ __forceinline__ uint32_t smem_u32(const void* p) {
    return (uint32_t)__cvta_generic_to_shared(p);
}
#define CP16(dst, src) asm volatile("cp.async.ca.shared.global [%0], [%1], 16;\n" :: "r"(dst), "l"(src))
#define LDSM4(r0, r1, r2, r3, addr) \
    asm volatile("ldmatrix.sync.aligned.m8n8.x4.shared.b16 {%0,%1,%2,%3}, [%4];" \
                 : "=r"(r0), "=r"(r1), "=r"(r2), "=r"(r3) : "r"(addr))

__device__ __forceinline__ unsigned f2u_ord(float f) {
    unsigned u = __float_as_uint(f);
    return (u & 0x80000000u) ? ~u : (u | 0x80000000u);
}
__device__ __forceinline__ float u2f_ord(unsigned u) {
    return (u & 0x80000000u) ? __uint_as_float(u ^ 0x80000000u) : __uint_as_float(~u);
}

// ---------------- k_pre: detect dtype, init counters, Wn/Wv transpose-split, A2T --
__global__ void k_pre(const void* EI, const float* __restrict__ Wn, const float* __restrict__ bn,
                      const float* __restrict__ Wv, const float* __restrict__ bv,
                      const float* __restrict__ A2) {
    int gtid = blockIdx.x * blockDim.x + threadIdx.x;   // 512*256 = 131072
    if (blockIdx.x == 0) {
        __shared__ int bad;
        if (threadIdx.x == 0) bad = 0;
        __syncthreads();
        long long v = ((const long long*)EI)[threadIdx.x];
        if (v < 0 || v >= N_NODES) atomicOr(&bad, 1);
        __syncthreads();
        if (threadIdx.x == 0) g_is64 = bad ? 0 : 1;
    }
    {   // Wn|Wv -> transposed hi/lo  (k row, j col of 512)
        int k = gtid >> 9, j = gtid & 511;
        float w = (j < 256) ? Wn[k * 256 + j] : Wv[k * 256 + j - 256];
        bf16 hi = __float2bfloat16_rn(w);
        g_WThi[j * 256 + k] = hi;
        g_WTlo[j * 256 + k] = __float2bfloat16_rn(w - __bfloat162float(hi));
    }
    if (gtid < N_NODES) { g_deg[gtid] = 0; g_cur[gtid] = 0; }
    if (gtid < 512) g_bbig[gtid] = (gtid < 256) ? bn[gtid] : bv[gtid - 256];
    if (gtid < 2048) { int h = gtid >> 8, d = gtid & 255; g_A2Tb[gtid] = __float2bfloat16_rn(A2[d * 8 + h]); }
    if (gtid == 0) { g_smax_u = 0u; g_ssum = 0.f; }
}

// ---------------- k_prep_fold: tiled GEMMs WqA/WkA/WeA + cvec --------------
__global__ void __launch_bounds__(256) k_prep_fold(const float* __restrict__ Wq, const float* __restrict__ bq,
                                                   const float* __restrict__ Wk, const float* __restrict__ bk,
                                                   const float* __restrict__ We, const float* __restrict__ be,
                                                   const float* __restrict__ A1, const float* __restrict__ a1) {
    int bid = blockIdx.x;
    int tid = threadIdx.x;
    if (bid == 144) {   // cvec
        int j = tid;
        float s = a1[j];
#pragma unroll 4
        for (int m = 0; m < 256; m++) {
            s += bq[m] * A1[m * 256 + j];
            s += bk[m] * A1[(256 + m) * 256 + j];
            s += be[m] * A1[(512 + m) * 256 + j];
        }
        g_cvec[j] = s;
        return;
    }
    int z, kt, jt, zoff;
    const float* W;
    if (bid < 64)       { z = 0; W = Wq; zoff = 0;   int t = bid;       kt = t >> 3; jt = t & 7; }
    else if (bid < 128) { z = 1; W = Wk; zoff = 256; int t = bid - 64;  kt = t >> 3; jt = t & 7; }
    else                { z = 2; W = We; zoff = 512; int t = bid - 128; kt = t >> 3; jt = t & 7; }
    int k0 = kt * 32, j0 = jt * 32;
    __shared__ float Ws[32][33], As[32][33];
    int ty = tid >> 4, tx = tid & 15;
    float acc[2][2] = {{0.f, 0.f}, {0.f, 0.f}};
    for (int m0 = 0; m0 < 256; m0 += 32) {
#pragma unroll
        for (int i = 0; i < 4; i++) {
            int id = i * 256 + tid;
            int r = id >> 5, c = id & 31;
            Ws[r][c] = W[(k0 + r) * 256 + m0 + c];
            As[r][c] = A1[(zoff + m0 + r) * 256 + j0 + c];
        }
        __syncthreads();
#pragma unroll 8
        for (int m = 0; m < 32; m++) {
            float a0 = Ws[ty * 2][m], a1v = Ws[ty * 2 + 1][m];
            float b0 = As[m][tx * 2], b1 = As[m][tx * 2 + 1];
            acc[0][0] += a0 * b0; acc[0][1] += a0 * b1;
            acc[1][0] += a1v * b0; acc[1][1] += a1v * b1;
        }
        __syncthreads();
    }
#pragma unroll
    for (int i = 0; i < 2; i++)
#pragma unroll
        for (int j = 0; j < 2; j++) {
            int k = k0 + ty * 2 + i, jg = j0 + tx * 2 + j;
            if (z < 2) g_WThi[(512 + z * 256 + jg) * 256 + k] = __float2bfloat16_rn(acc[i][j]);
            else       g_WeATb[jg * 64 + k] = __float2bfloat16_rn(acc[i][j]);
        }
}

// ---------------- k_convX: X -> hi/lo bf16 (float4 vectorized) -------------
__global__ void k_convX(const float* __restrict__ X) {
    int i = blockIdx.x * blockDim.x + threadIdx.x;   // over 1M float4s
    float4 v = ((const float4*)X)[i];
    bf162 h0 = __floats2bfloat162_rn(v.x, v.y);
    bf162 h1 = __floats2bfloat162_rn(v.z, v.w);
    bf162 l0 = __floats2bfloat162_rn(v.x - __bfloat162float(h0.x), v.y - __bfloat162float(h0.y));
    bf162 l1 = __floats2bfloat162_rn(v.z - __bfloat162float(h1.x), v.w - __bfloat162float(h1.y));
    uint2 uh, ul;
    uh.x = *(uint32_t*)&h0; uh.y = *(uint32_t*)&h1;
    ul.x = *(uint32_t*)&l0; ul.y = *(uint32_t*)&l1;
    ((uint2*)g_Xhi)[i] = uh;
    ((uint2*)g_Xlo)[i] = ul;
}

// ---------------- node GEMM: [16384,256] @ [256,1024], mma.sync + ldmatrix --
// bx<2 (h): 3-pass split bf16 -> fp32.  bx 2,3 (v): 1-pass -> bf16 row-major.
// bx>=4 (Pq|Pk): 1-pass -> bf16 pair-grouped layout (32B/lane stores).
#define NGM_SMEM (2 * 4 * 128 * 40 * 2)   // 81920 bytes

__global__ void __launch_bounds__(256) k_node_gemm() {
    extern __shared__ bf16 smN[];
    const int tid = threadIdx.x;
    const int lane = tid & 31, wid = tid >> 5;
    const int wm = wid & 3, wn = wid >> 2;
    const int bx = blockIdx.x;
    const int m0 = blockIdx.y * 128, n0 = bx * 128;
    const bool full3 = (bx < 2);

    // ldmatrix per-lane offsets (element units, stride 40/row)
    const int tile = lane >> 3, tin = lane & 7;
    const int aOff = (wm * 32 + (tile & 1) * 8 + tin) * 40 + (tile >> 1) * 8;  // + mt*640 + kh*16
    const int bOff = (wn * 64 + (tile >> 1) * 8 + tin) * 40 + (tile & 1) * 8;  // + nt2*640 + kh*16

    float acc[2][8][4];
#pragma unroll
    for (int mt = 0; mt < 2; mt++)
#pragma unroll
        for (int nt = 0; nt < 8; nt++)
#pragma unroll
            for (int c = 0; c < 4; c++) acc[mt][nt][c] = 0.f;

    auto load_chunk = [&](int c, int buf) {
        int k0 = c * 32;
        if (full3) {
#pragma unroll
            for (int j = 0; j < 8; j++) {
                int id = j * 256 + tid;
                int arr = id >> 9;
                int rem = id & 511;
                int row = rem >> 2, seg = rem & 3;
                const bf16* src;
                if (arr == 0)      src = g_Xhi  + (m0 + row) * 256 + k0 + seg * 8;
                else if (arr == 1) src = g_Xlo  + (m0 + row) * 256 + k0 + seg * 8;
                else if (arr == 2) src = g_WThi + (n0 + row) * 256 + k0 + seg * 8;
                else               src = g_WTlo + (n0 + row) * 256 + k0 + seg * 8;
                uint32_t dst = smem_u32(smN + buf * 20480 + arr * 5120 + row * 40 + seg * 8);
                CP16(dst, src);
            }
        } else {
#pragma unroll
            for (int j = 0; j < 4; j++) {
                int id = j * 256 + tid;
                int sel = id >> 9;
                int rem = id & 511;
                int row = rem >> 2, seg = rem & 3;
                const bf16* src = (sel == 0) ? g_Xhi + (m0 + row) * 256 + k0 + seg * 8
                                             : g_WThi + (n0 + row) * 256 + k0 + seg * 8;
                uint32_t dst = smem_u32(smN + buf * 20480 + (sel * 2) * 5120 + row * 40 + seg * 8);
                CP16(dst, src);
            }
        }
        asm volatile("cp.async.commit_group;\n" ::);
    };

    load_chunk(0, 0);

    for (int c = 0; c < 8; c++) {
        if (c < 7) load_chunk(c + 1, (c + 1) & 1);
        if (c < 7) asm volatile("cp.async.wait_group 1;\n" ::);
        else       asm volatile("cp.async.wait_group 0;\n" ::);
        __syncthreads();

        const int bb = (c & 1) * 20480;
        const bf16* sAh = smN + bb;
        const bf16* sAl = smN + bb + 5120;
        const bf16* sBh = smN + bb + 2 * 5120;
        const bf16* sBl = smN + bb + 3 * 5120;

#pragma unroll
        for (int kh = 0; kh < 2; kh++) {
            uint32_t Ah[2][4], Bh[8][2];
#pragma unroll
            for (int mt = 0; mt < 2; mt++)
                LDSM4(Ah[mt][0], Ah[mt][1], Ah[mt][2], Ah[mt][3],
                      smem_u32(sAh + aOff + mt * 640 + kh * 16));
#pragma unroll
            for (int nt2 = 0; nt2 < 4; nt2++) {
                uint32_t b00, b01, b10, b11;
                LDSM4(b00, b01, b10, b11, smem_u32(sBh + bOff + nt2 * 640 + kh * 16));
                Bh[2 * nt2][0] = b00; Bh[2 * nt2][1] = b01;
                Bh[2 * nt2 + 1][0] = b10; Bh[2 * nt2 + 1][1] = b11;
            }
            if (full3) {
                uint32_t Al[2][4], Bl[8][2];
#pragma unroll
                for (int mt = 0; mt < 2; mt++)
                    LDSM4(Al[mt][0], Al[mt][1], Al[mt][2], Al[mt][3],
                          smem_u32(sAl + aOff + mt * 640 + kh * 16));
#pragma unroll
                for (int nt2 = 0; nt2 < 4; nt2++) {
                    uint32_t b00, b01, b10, b11;
                    LDSM4(b00, b01, b10, b11, smem_u32(sBl + bOff + nt2 * 640 + kh * 16));
                    Bl[2 * nt2][0] = b00; Bl[2 * nt2][1] = b01;
                    Bl[2 * nt2 + 1][0] = b10; Bl[2 * nt2 + 1][1] = b11;
                }
#pragma unroll
                for (int mt = 0; mt < 2; mt++)
#pragma unroll
                    for (int nt = 0; nt < 8; nt++) {
                        mma16816(acc[mt][nt], Ah[mt][0], Ah[mt][1], Ah[mt][2], Ah[mt][3], Bh[nt][0], Bh[nt][1]);
                        mma16816(acc[mt][nt], Ah[mt][0], Ah[mt][1], Ah[mt][2], Ah[mt][3], Bl[nt][0], Bl[nt][1]);
                        mma16816(acc[mt][nt], Al[mt][0], Al[mt][1], Al[mt][2], Al[mt][3], Bh[nt][0], Bh[nt][1]);
                    }
            } else {
#pragma unroll
                for (int mt = 0; mt < 2; mt++)
#pragma unroll
                    for (int nt = 0; nt < 8; nt++)
                        mma16816(acc[mt][nt], Ah[mt][0], Ah[mt][1], Ah[mt][2], Ah[mt][3], Bh[nt][0], Bh[nt][1]);
            }
        }
        __syncthreads();
    }

    if (bx < 4) {
#pragma unroll
        for (int mt = 0; mt < 2; mt++) {
            int r0 = m0 + wm * 32 + mt * 16 + (lane >> 2);
#pragma unroll
            for (int nt = 0; nt < 8; nt++) {
                int colg = n0 + wn * 64 + nt * 8 + (lane & 3) * 2;
                float b0 = g_bbig[colg], b1 = g_bbig[colg + 1];
                if (bx < 2) {
                    *(float2*)(g_h + r0 * 256 + colg) = make_float2(acc[mt][nt][0] + b0, acc[mt][nt][1] + b1);
                    *(float2*)(g_h + (r0 + 8) * 256 + colg) = make_float2(acc[mt][nt][2] + b0, acc[mt][nt][3] + b1);
                } else {
                    int cc = colg - 256;
                    *(bf162*)(g_vb + r0 * 256 + cc) = __floats2bfloat162_rn(acc[mt][nt][0] + b0, acc[mt][nt][1] + b1);
                    *(bf162*)(g_vb + (r0 + 8) * 256 + cc) = __floats2bfloat162_rn(acc[mt][nt][2] + b0, acc[mt][nt][3] + b1);
                }
            }
        }
    } else {
        // pair-grouped layout: per thread 8 consecutive p-pairs -> two uint4 per row
        int base = n0 - 512 + wn * 64;       // 0..448
        int arr = base >> 8;
        int p0 = (base >> 3) & 31;
#pragma unroll
        for (int mt = 0; mt < 2; mt++) {
            int r0 = m0 + wm * 32 + mt * 16 + (lane >> 2);
            uint32_t u0[8], u1[8];
#pragma unroll
            for (int nt = 0; nt < 8; nt++) {
                u0[nt] = pack_bf16(acc[mt][nt][0], acc[mt][nt][1]);
                u1[nt] = pack_bf16(acc[mt][nt][2], acc[mt][nt][3]);
            }
            bf16* d0 = g_nodeqk + (size_t)r0 * 512 + arr * 256 + (lane & 3) * 64 + p0 * 2;
            bf16* d1 = g_nodeqk + (size_t)(r0 + 8) * 512 + arr * 256 + (lane & 3) * 64 + p0 * 2;
            *(uint4*)d0       = make_uint4(u0[0], u0[1], u0[2], u0[3]);
            *(uint4*)(d0 + 8) = make_uint4(u0[4], u0[5], u0[6], u0[7]);
            *(uint4*)d1       = make_uint4(u1[0], u1[1], u1[2], u1[3]);
            *(uint4*)(d1 + 8) = make_uint4(u1[4], u1[5], u1[6], u1[7]);
        }
    }
}

// ---------------- fused edge kernel (mma.sync + ldmatrix + max + hist) -----
#define E_SEF   0
#define E_SWT   18432
#define E_SA2T  55296
#define E_SC    59520
#define E_SA2   60544
#define E_SSRC  60576
#define E_STGT  61088
#define EDGE_SMEM 61600

__global__ void __launch_bounds__(256) k_edge(const float* __restrict__ EF,
                                              const void* __restrict__ EI,
                                              const float* __restrict__ a2) {
    extern __shared__ char smE[];
    bf16*  sEF  = (bf16*)(smE + E_SEF);     // [128][72]
    bf16*  sWT  = (bf16*)(smE + E_SWT);     // [256][72]
    bf16*  sA2T = (bf16*)(smE + E_SA2T);    // [8][264]
    float* sc   = (float*)(smE + E_SC);
    float* sa2  = (float*)(smE + E_SA2);
    int*   ssrc = (int*)(smE + E_SSRC);
    int*   stgt = (int*)(smE + E_STGT);

    const int tid = threadIdx.x;
    const int lane = tid & 31, wid = tid >> 5;
    const int e0base = blockIdx.x * 128;
    const int is64 = g_is64;

#pragma unroll
    for (int j = 0; j < 8; j++) {
        int id = j * 256 + tid;
        int row = id >> 4, seg = id & 15;
        float4 v = *(const float4*)(EF + ((size_t)(e0base + row)) * 64 + seg * 4);
        bf162 p0 = __floats2bfloat162_rn(v.x, v.y);
        bf162 p1 = __floats2bfloat162_rn(v.z, v.w);
        uint2 u; u.x = *(uint32_t*)&p0; u.y = *(uint32_t*)&p1;
        *(uint2*)(sEF + row * 72 + seg * 4) = u;
    }
#pragma unroll
    for (int j = 0; j < 8; j++) {
        int id = j * 256 + tid;
        int row = id >> 3, seg = id & 7;
        uint4 v = *(const uint4*)(g_WeATb + row * 64 + seg * 8);
        *(uint4*)(sWT + row * 72 + seg * 8) = v;
    }
    {   // A2T: full coverage — 256 threads x 8 elements = 2048
        int row = tid >> 5, seg = tid & 31;
        uint4 v = *(const uint4*)(g_A2Tb + row * 256 + seg * 8);
        *(uint4*)(sA2T + row * 264 + seg * 8) = v;
    }
    sc[tid] = g_cvec[tid];
    if (tid < 8) sa2[tid] = a2[tid];
    if (tid < 128) {
        int sn = ld_idx(EI, e0base + tid, is64);
        ssrc[tid] = sn;
        stgt[tid] = ld_idx(EI, N_EDGES + e0base + tid, is64);
        atomicAdd(&g_deg[sn], 1);        // fused histogram
    }
    __syncthreads();

    // A fragments for this warp's 16 edges via ldmatrix
    const int tile = lane >> 3, tin = lane & 7;
    const int aOffE = (wid * 16 + (tile & 1) * 8 + tin) * 72 + (tile >> 1) * 8;
    const int bOffE = ((tile >> 1) * 8 + tin) * 72 + (tile & 1) * 8;
    uint32_t Af[4][4];
#pragma unroll
    for (int kh = 0; kh < 4; kh++)
        LDSM4(Af[kh][0], Af[kh][1], Af[kh][2], Af[kh][3], smem_u32(sEF + aOffE + kh * 16));

    const int sn0 = ssrc[wid * 16 + (lane >> 2)];
    const int sn1 = ssrc[wid * 16 + (lane >> 2) + 8];
    const int tn0 = stgt[wid * 16 + (lane >> 2)];
    const int tn1 = stgt[wid * 16 + (lane >> 2) + 8];
    const int j4 = lane & 3;

    float hacc[4] = {0.f, 0.f, 0.f, 0.f};

#pragma unroll
    for (int q4 = 0; q4 < 4; q4++) {
        // prefetch q/k gathers: 32B contiguous per lane per array (sector-perfect)
        uint4 qv[2][2], kv[2][2];
#pragma unroll
        for (int i = 0; i < 2; i++) {
            int sn = i ? sn1 : sn0;
            int tn = i ? tn1 : tn0;
            const bf16* qb = g_nodeqk + (size_t)sn * 512 + j4 * 64 + q4 * 16;
            const bf16* kb = g_nodeqk + (size_t)tn * 512 + 256 + j4 * 64 + q4 * 16;
            qv[i][0] = *(const uint4*)qb; qv[i][1] = *(const uint4*)(qb + 8);
            kv[i][0] = *(const uint4*)kb; kv[i][1] = *(const uint4*)(kb + 8);
        }

        float acc[8][4];
#pragma unroll
        for (int nt = 0; nt < 8; nt++)
#pragma unroll
            for (int c = 0; c < 4; c++) acc[nt][c] = 0.f;

#pragma unroll
        for (int kh = 0; kh < 4; kh++) {
            uint32_t B[8][2];
#pragma unroll
            for (int nt2 = 0; nt2 < 4; nt2++) {
                uint32_t b00, b01, b10, b11;
                LDSM4(b00, b01, b10, b11,
                      smem_u32(sWT + (q4 * 64 + nt2 * 16) * 72 + bOffE + kh * 16));
                B[2 * nt2][0] = b00; B[2 * nt2][1] = b01;
                B[2 * nt2 + 1][0] = b10; B[2 * nt2 + 1][1] = b11;
            }
#pragma unroll
            for (int nt = 0; nt < 8; nt++)
                mma16816(acc[nt], Af[kh][0], Af[kh][1], Af[kh][2], Af[kh][3], B[nt][0], B[nt][1]);
        }

        uint32_t zbuf[4][4];
#pragma unroll
        for (int nt = 0; nt < 8; nt++) {
            int colbase = q4 * 64 + nt * 8 + j4 * 2;
            float cc0 = sc[colbase], cc1 = sc[colbase + 1];
            int tt = nt >> 1;
#pragma unroll
            for (int i = 0; i < 2; i++) {
                bf162 qp = ((const bf162*)qv[i])[nt];
                bf162 kp = ((const bf162*)kv[i])[nt];
                float z0 = lrelu(acc[nt][2 * i]     + __bfloat162float(qp.x) + __bfloat162float(kp.x) + cc0);
                float z1 = lrelu(acc[nt][2 * i + 1] + __bfloat162float(qp.y) + __bfloat162float(kp.y) + cc1);
                zbuf[tt][(nt & 1) * 2 + i] = pack_bf16(z0, z1);
            }
        }

#pragma unroll
        for (int tt = 0; tt < 4; tt++) {
            int kcol = q4 * 64 + tt * 16 + j4 * 2;
            uint32_t b0 = *(const uint32_t*)(sA2T + (lane >> 2) * 264 + kcol);
            uint32_t b1 = *(const uint32_t*)(sA2T + (lane >> 2) * 264 + kcol + 8);
            mma16816(hacc, zbuf[tt][0], zbuf[tt][1], zbuf[tt][2], zbuf[tt][3], b0, b1);
        }
    }

    float a20 = sa2[j4 * 2], a21 = sa2[j4 * 2 + 1];
    float s0 = lrelu(hacc[0] + a20) + lrelu(hacc[1] + a21);
    float s1 = lrelu(hacc[2] + a20) + lrelu(hacc[3] + a21);
    s0 += __shfl_xor_sync(0xffffffffu, s0, 1);
    s0 += __shfl_xor_sync(0xffffffffu, s0, 2);
    s1 += __shfl_xor_sync(0xffffffffu, s1, 1);
    s1 += __shfl_xor_sync(0xffffffffu, s1, 2);
    if ((lane & 3) == 0) {
        int eg = e0base + wid * 16 + (lane >> 2);
        g_s[eg] = s0 * 0.125f;
        g_s[eg + 8] = s1 * 0.125f;
    }
    // fused block max -> atomicMax
    float mval = fmaxf(s0, s1) * 0.125f;
#pragma unroll
    for (int off = 4; off < 32; off <<= 1)
        mval = fmaxf(mval, __shfl_xor_sync(0xffffffffu, mval, off));
    __shared__ float swm[8];
    if (lane == 0) swm[wid] = mval;
    __syncthreads();
    if (tid == 0) {
        float m = swm[0];
#pragma unroll
        for (int i = 1; i < 8; i++) m = fmaxf(m, swm[i]);
        atomicMax(&g_smax_u, f2u_ord(m));
    }
}

// ---------------- counting sort scan ----------------
__global__ void k_scan() {
    int tid = threadIdx.x;
    int x[16];
    int base = tid * 16;
    int tot = 0;
#pragma unroll
    for (int i = 0; i < 16; i++) { x[i] = g_deg[base + i]; tot += x[i]; }
    int v = tot;
#pragma unroll
    for (int off = 1; off < 32; off <<= 1) {
        int t = __shfl_up_sync(0xffffffffu, v, off);
        if ((tid & 31) >= off) v += t;
    }
    __shared__ int sw[32];
    if ((tid & 31) == 31) sw[tid >> 5] = v;
    __syncthreads();
    if (tid < 32) {
        int t = sw[tid];
        int v2 = t;
#pragma unroll
        for (int off = 1; off < 32; off <<= 1) {
            int u = __shfl_up_sync(0xffffffffu, v2, off);
            if (tid >= off) v2 += u;
        }
        sw[tid] = v2 - t;
    }
    __syncthreads();
    int run = sw[tid >> 5] + v - tot;
#pragma unroll
    for (int i = 0; i < 16; i++) { g_off[base + i] = run; run += x[i]; }
    if (tid == 1023) g_off[N_NODES] = run;
}

// ---------------- place + exp-sum fused ----------------
__global__ void k_place_ssum(const void* __restrict__ EI) {
    int e = blockIdx.x * blockDim.x + threadIdx.x;
    int is64 = g_is64;
    float mx = u2f_ord(g_smax_u);
    float s = 0.f;
    if (e < N_EDGES) {
        int sn = ld_idx(EI, e, is64);
        int p = atomicAdd(&g_cur[sn], 1);
        g_eidx[g_off[sn] + p] = e;
        s = expf(g_s[e] - mx);
    }
#pragma unroll
    for (int off = 16; off; off >>= 1) s += __shfl_xor_sync(0xffffffffu, s, off);
    __shared__ float sm[8];
    if ((threadIdx.x & 31) == 0) sm[threadIdx.x >> 5] = s;
    __syncthreads();
    if (threadIdx.x == 0) {
        for (int i = 1; i < 8; i++) s += sm[i];
        atomicAdd(&g_ssum, s);
    }
}

// ---------------- final: weights + gather w*v[tgt] (bf16), add h, LayerNorm --
__global__ void __launch_bounds__(256) k_final(const void* __restrict__ EI,
                                               const float* __restrict__ gamma,
                                               const float* __restrict__ beta,
                                               float* __restrict__ out) {
    int n = blockIdx.x;
    int d = threadIdx.x;
    int is64 = g_is64;
    float mx = u2f_ord(g_smax_u);
    float rinv = 1.f / g_ssum;
    float acc = g_h[n * 256 + d];
    int beg = g_off[n], end = g_off[n + 1];

    __shared__ float swv[256];
    __shared__ int stg[256];
    for (int chunk = beg; chunk < end; chunk += 256) {
        int m = min(256, end - chunk);
        if (d < m) {
            int e = g_eidx[chunk + d];
            swv[d] = expf(g_s[e] - mx) * rinv;
            stg[d] = ld_idx(EI, N_EDGES + e, is64);
        }
        __syncthreads();
        for (int i = 0; i < m; i++)
            acc += swv[i] * __bfloat162float(g_vb[(size_t)stg[i] * 256 + d]);
        __syncthreads();
    }

    float v1 = acc, v2 = acc * acc;
#pragma unroll
    for (int off = 16; off; off >>= 1) {
        v1 += __shfl_xor_sync(0xffffffffu, v1, off);
        v2 += __shfl_xor_sync(0xffffffffu, v2, off);
    }
    __shared__ float s1[8], s2[8];
    __shared__ float s_mu, s_rstd;
    int wid = d >> 5, lane = d & 31;
    if (lane == 0) { s1[wid] = v1; s2[wid] = v2; }
    __syncthreads();
    if (d == 0) {
        float S = 0.f, Q = 0.f;
        for (int i = 0; i < 8; i++) { S += s1[i]; Q += s2[i]; }
        float mu = S * (1.f / 256.f);
        float var = Q * (1.f / 256.f) - mu * mu;
        s_mu = mu;
        s_rstd = rsqrtf(var + 1e-5f);
    }
    __syncthreads();
    out[n * 256 + d] = (acc - s_mu) * s_rstd * gamma[d] + beta[d];
}

// ---------------- launch ----------------
extern "C" void kernel_launch(void* const* d_in, const int* in_sizes, int n_in,
                              void* d_out, int out_size) {
    const float* X     = (const float*)d_in[0];
    const void*  EI    = d_in[1];
    const float* EF    = (const float*)d_in[2];
    const float* Wn    = (const float*)d_in[3];
    const float* bn    = (const float*)d_in[4];
    const float* Wq    = (const float*)d_in[5];
    const float* bq    = (const float*)d_in[6];
    const float* Wk    = (const float*)d_in[7];
    const float* bk    = (const float*)d_in[8];
    const float* Wv    = (const float*)d_in[9];
    const float* bv    = (const float*)d_in[10];
    const float* We    = (const float*)d_in[11];
    const float* be    = (const float*)d_in[12];
    const float* A1    = (const float*)d_in[13];
    const float* a1    = (const float*)d_in[14];
    const float* A2    = (const float*)d_in[15];
    const float* a2    = (const float*)d_in[16];
    const float* gamma = (const float*)d_in[17];
    const float* beta  = (const float*)d_in[18];
    float* out = (float*)d_out;

    cudaFuncSetAttribute(k_node_gemm, cudaFuncAttributeMaxDynamicSharedMemorySize, NGM_SMEM);
    cudaFuncSetAttribute(k_edge, cudaFuncAttributeMaxDynamicSharedMemorySize, EDGE_SMEM);

    k_pre<<<512, 256>>>(EI, Wn, bn, Wv, bv, A2);
    k_prep_fold<<<145, 256>>>(Wq, bq, Wk, bk, We, be, A1, a1);
    k_convX<<<4096, 256>>>(X);
    k_node_gemm<<<dim3(8, 128), 256, NGM_SMEM>>>();
    k_edge<<<2048, 256, EDGE_SMEM>>>(EF, EI, a2);
    k_scan<<<1, 1024>>>();
    k_place_ssum<<<1024, 256>>>(EI);
    k_final<<<16384, 256>>>(EI, gamma, beta, out);
}

// round 9
// speedup vs baseline: 2.7642x; 1.0668x over previous
#include <cuda_runtime.h>
#include <cuda_bf16.h>
#include <math.h>
#include <stdint.h>

#define N_NODES 16384
#define N_EDGES 262144
#define DN 256
#define DE 64
#define NH 8

typedef __nv_bfloat16 bf16;
typedef __nv_bfloat162 bf162;

// ---------------- device scratch (static allocations only) ----------------
__device__ bf16  g_WThi[1024 * 256];           // W^T [n][k]: Wn|Wv|WqA1q|WkA1k (hi)
__device__ bf16  g_WTlo[1024 * 256];           // lo (only n<512 written/used)
__device__ float g_bbig[512];                  // bn | bv
__device__ bf16  g_Xhi[N_NODES * 256];
__device__ bf16  g_Xlo[N_NODES * 256];
__device__ bf16  g_WeATb[256 * 64];            // (We@A1e)^T [n=256][k=64] bf16
__device__ float g_cvec[DN];                   // bq@A1q + bk@A1k + be@A1e + a1
__device__ bf16  g_A2Tb[8 * 256];              // A2^T [h][d] bf16
__device__ float g_h[N_NODES * 256];           // h (fp32)
__device__ bf16  g_vb[N_NODES * 256];          // v (bf16)
// Pq|Pk per node, PAIR-GROUPED layout: [node][arr(q=0,k=1)][j=0..3][p=0..31]
// where original col = p*8 + 2j (+1). 512 bf16 per node.
__device__ bf16  g_nodeqk[N_NODES * 512];
__device__ float g_s[N_EDGES];                 // per-edge pre-softmax score
__device__ int   g_deg[N_NODES];
__device__ int   g_off[N_NODES + 1];
__device__ int   g_cur[N_NODES];
__device__ int   g_eidx[N_EDGES];
__device__ unsigned int g_smax_u;
__device__ float g_ssum;
__device__ int   g_is64;

__device__ __forceinline__ float lrelu(float x) { return x > 0.f ? x : 0.2f * x; }

__device__ __forceinline__ int ld_idx(const void* EI, int pos, int is64) {
    if (is64) return (int)((const long long*)EI)[pos];
    return ((const int*)EI)[pos];
}

__device__ __forceinline__ uint32_t pack_bf16(float x, float y) {
    bf162 p = __floats2bfloat162_rn(x, y);
    return *reinterpret_cast<uint32_t*>(&p);
}

__device__ __forceinline__ void mma16816(float* d, uint32_t a0, uint32_t a1, uint32_t a2, uint32_t a3,
                                         uint32_t b0, uint32_t b1) {
    asm volatile(
        "mma.sync.aligned.m16n8k16.row.col.f32.bf16.bf16.f32 "
        "{%0,%1,%2,%3},{%4,%5,%6,%7},{%8,%9},{%0,%1,%2,%3};"
        : "+f"(d[0]), "+f"(d[1]), "+f"(d[2]), "+f"(d[3])
        : "r"(a0), "r"(a1), "r"(a2), "r"(a3), "r"(b0), "r"(b1));
}

__device__ __forceinline__ uint32_t smem_u32(const void* p) {
    return (uint32_t)__cvta_generic_to_shared(p);
}
#define CP16(dst, src) asm volatile("cp.async.ca.shared.global [%0], [%1], 16;\n" :: "r"(dst), "l"(src))
#define LDSM4(r0, r1, r2, r3, addr) \
    asm volatile("ldmatrix.sync.aligned.m8n8.x4.shared.b16 {%0,%1,%2,%3}, [%4];" \
                 : "=r"(r0), "=r"(r1), "=r"(r2), "=r"(r3) : "r"(addr))

__device__ __forceinline__ unsigned f2u_ord(float f) {
    unsigned u = __float_as_uint(f);
    return (u & 0x80000000u) ? ~u : (u | 0x80000000u);
}
__device__ __forceinline__ float u2f_ord(unsigned u) {
    return (u & 0x80000000u) ? __uint_as_float(u ^ 0x80000000u) : __uint_as_float(~u);
}

// ---------------- k_pre: dtype detect + init + Wn/Wv transpose-split + A2T + convX --
// grid 4096 x 256. Blocks 0..511 do prep work; ALL blocks convert X (1M float4s).
__global__ void k_pre(const void* EI, const float* __restrict__ Wn, const float* __restrict__ bn,
                      const float* __restrict__ Wv, const float* __restrict__ bv,
                      const float* __restrict__ A2, const float* __restrict__ X) {
    int gtid = blockIdx.x * blockDim.x + threadIdx.x;
    // ---- convX: all 1048576 float4s ----
    {
        float4 v = ((const float4*)X)[gtid];
        bf162 h0 = __floats2bfloat162_rn(v.x, v.y);
        bf162 h1 = __floats2bfloat162_rn(v.z, v.w);
        bf162 l0 = __floats2bfloat162_rn(v.x - __bfloat162float(h0.x), v.y - __bfloat162float(h0.y));
        bf162 l1 = __floats2bfloat162_rn(v.z - __bfloat162float(h1.x), v.w - __bfloat162float(h1.y));
        uint2 uh, ul;
        uh.x = *(uint32_t*)&h0; uh.y = *(uint32_t*)&h1;
        ul.x = *(uint32_t*)&l0; ul.y = *(uint32_t*)&l1;
        ((uint2*)g_Xhi)[gtid] = uh;
        ((uint2*)g_Xlo)[gtid] = ul;
    }
    if (gtid >= 131072) return;
    if (blockIdx.x == 0) {
        __shared__ int bad;
        if (threadIdx.x == 0) bad = 0;
        __syncthreads();
        long long v = ((const long long*)EI)[threadIdx.x];
        if (v < 0 || v >= N_NODES) atomicOr(&bad, 1);
        __syncthreads();
        if (threadIdx.x == 0) g_is64 = bad ? 0 : 1;
    }
    {   // Wn|Wv -> transposed hi/lo  (k row, j col of 512)
        int k = gtid >> 9, j = gtid & 511;
        float w = (j < 256) ? Wn[k * 256 + j] : Wv[k * 256 + j - 256];
        bf16 hi = __float2bfloat16_rn(w);
        g_WThi[j * 256 + k] = hi;
        g_WTlo[j * 256 + k] = __float2bfloat16_rn(w - __bfloat162float(hi));
    }
    if (gtid < N_NODES) { g_deg[gtid] = 0; g_cur[gtid] = 0; }
    if (gtid < 512) g_bbig[gtid] = (gtid < 256) ? bn[gtid] : bv[gtid - 256];
    if (gtid < 2048) { int h = gtid >> 8, d = gtid & 255; g_A2Tb[gtid] = __float2bfloat16_rn(A2[d * 8 + h]); }
    if (gtid == 0) { g_smax_u = 0u; g_ssum = 0.f; }
}

// ---------------- k_prep_fold: tiled GEMMs WqA/WkA/WeA + cvec --------------
__global__ void __launch_bounds__(256) k_prep_fold(const float* __restrict__ Wq, const float* __restrict__ bq,
                                                   const float* __restrict__ Wk, const float* __restrict__ bk,
                                                   const float* __restrict__ We, const float* __restrict__ be,
                                                   const float* __restrict__ A1, const float* __restrict__ a1) {
    int bid = blockIdx.x;
    int tid = threadIdx.x;
    if (bid == 144) {   // cvec
        int j = tid;
        float s = a1[j];
#pragma unroll 4
        for (int m = 0; m < 256; m++) {
            s += bq[m] * A1[m * 256 + j];
            s += bk[m] * A1[(256 + m) * 256 + j];
            s += be[m] * A1[(512 + m) * 256 + j];
        }
        g_cvec[j] = s;
        return;
    }
    int z, kt, jt, zoff;
    const float* W;
    if (bid < 64)       { z = 0; W = Wq; zoff = 0;   int t = bid;       kt = t >> 3; jt = t & 7; }
    else if (bid < 128) { z = 1; W = Wk; zoff = 256; int t = bid - 64;  kt = t >> 3; jt = t & 7; }
    else                { z = 2; W = We; zoff = 512; int t = bid - 128; kt = t >> 3; jt = t & 7; }
    int k0 = kt * 32, j0 = jt * 32;
    __shared__ float Ws[32][33], As[32][33];
    int ty = tid >> 4, tx = tid & 15;
    float acc[2][2] = {{0.f, 0.f}, {0.f, 0.f}};
    for (int m0 = 0; m0 < 256; m0 += 32) {
#pragma unroll
        for (int i = 0; i < 4; i++) {
            int id = i * 256 + tid;
            int r = id >> 5, c = id & 31;
            Ws[r][c] = W[(k0 + r) * 256 + m0 + c];
            As[r][c] = A1[(zoff + m0 + r) * 256 + j0 + c];
        }
        __syncthreads();
#pragma unroll 8
        for (int m = 0; m < 32; m++) {
            float a0 = Ws[ty * 2][m], a1v = Ws[ty * 2 + 1][m];
            float b0 = As[m][tx * 2], b1 = As[m][tx * 2 + 1];
            acc[0][0] += a0 * b0; acc[0][1] += a0 * b1;
            acc[1][0] += a1v * b0; acc[1][1] += a1v * b1;
        }
        __syncthreads();
    }
#pragma unroll
    for (int i = 0; i < 2; i++)
#pragma unroll
        for (int j = 0; j < 2; j++) {
            int k = k0 + ty * 2 + i, jg = j0 + tx * 2 + j;
            if (z < 2) g_WThi[(512 + z * 256 + jg) * 256 + k] = __float2bfloat16_rn(acc[i][j]);
            else       g_WeATb[jg * 64 + k] = __float2bfloat16_rn(acc[i][j]);
        }
}

// ---------------- node GEMM: [16384,256] @ [256,1024], mma.sync + ldmatrix --
// Single-sync pipelined mainloop: {wait0; sync; load c+1; compute c}.
#define NGM_SMEM (2 * 4 * 128 * 40 * 2)   // 81920 bytes

__global__ void __launch_bounds__(256) k_node_gemm() {
    extern __shared__ bf16 smN[];
    const int tid = threadIdx.x;
    const int lane = tid & 31, wid = tid >> 5;
    const int wm = wid & 3, wn = wid >> 2;
    const int bx = blockIdx.x;
    const int m0 = blockIdx.y * 128, n0 = bx * 128;
    const bool full3 = (bx < 2);

    // ldmatrix per-lane offsets (element units, stride 40/row)
    const int tile = lane >> 3, tin = lane & 7;
    const int aOff = (wm * 32 + (tile & 1) * 8 + tin) * 40 + (tile >> 1) * 8;
    const int bOff = (wn * 64 + (tile >> 1) * 8 + tin) * 40 + (tile & 1) * 8;

    float acc[2][8][4];
#pragma unroll
    for (int mt = 0; mt < 2; mt++)
#pragma unroll
        for (int nt = 0; nt < 8; nt++)
#pragma unroll
            for (int c = 0; c < 4; c++) acc[mt][nt][c] = 0.f;

    auto load_chunk = [&](int c, int buf) {
        int k0 = c * 32;
        if (full3) {
#pragma unroll
            for (int j = 0; j < 8; j++) {
                int id = j * 256 + tid;
                int arr = id >> 9;
                int rem = id & 511;
                int row = rem >> 2, seg = rem & 3;
                const bf16* src;
                if (arr == 0)      src = g_Xhi  + (m0 + row) * 256 + k0 + seg * 8;
                else if (arr == 1) src = g_Xlo  + (m0 + row) * 256 + k0 + seg * 8;
                else if (arr == 2) src = g_WThi + (n0 + row) * 256 + k0 + seg * 8;
                else               src = g_WTlo + (n0 + row) * 256 + k0 + seg * 8;
                uint32_t dst = smem_u32(smN + buf * 20480 + arr * 5120 + row * 40 + seg * 8);
                CP16(dst, src);
            }
        } else {
#pragma unroll
            for (int j = 0; j < 4; j++) {
                int id = j * 256 + tid;
                int sel = id >> 9;
                int rem = id & 511;
                int row = rem >> 2, seg = rem & 3;
                const bf16* src = (sel == 0) ? g_Xhi + (m0 + row) * 256 + k0 + seg * 8
                                             : g_WThi + (n0 + row) * 256 + k0 + seg * 8;
                uint32_t dst = smem_u32(smN + buf * 20480 + (sel * 2) * 5120 + row * 40 + seg * 8);
                CP16(dst, src);
            }
        }
        asm volatile("cp.async.commit_group;\n" ::);
    };

    load_chunk(0, 0);

    for (int c = 0; c < 8; c++) {
        asm volatile("cp.async.wait_group 0;\n" ::);
        __syncthreads();
        // barrier proves: (a) every thread's group-c cp.async done -> buf c%2
        // readable; (b) all warps finished compute c-1 -> buf (c+1)%2 free.
        if (c < 7) load_chunk(c + 1, (c + 1) & 1);

        const int bb = (c & 1) * 20480;
        const bf16* sAh = smN + bb;
        const bf16* sAl = smN + bb + 5120;
        const bf16* sBh = smN + bb + 2 * 5120;
        const bf16* sBl = smN + bb + 3 * 5120;

#pragma unroll
        for (int kh = 0; kh < 2; kh++) {
            uint32_t Ah[2][4], Bh[8][2];
#pragma unroll
            for (int mt = 0; mt < 2; mt++)
                LDSM4(Ah[mt][0], Ah[mt][1], Ah[mt][2], Ah[mt][3],
                      smem_u32(sAh + aOff + mt * 640 + kh * 16));
#pragma unroll
            for (int nt2 = 0; nt2 < 4; nt2++) {
                uint32_t b00, b01, b10, b11;
                LDSM4(b00, b01, b10, b11, smem_u32(sBh + bOff + nt2 * 640 + kh * 16));
                Bh[2 * nt2][0] = b00; Bh[2 * nt2][1] = b01;
                Bh[2 * nt2 + 1][0] = b10; Bh[2 * nt2 + 1][1] = b11;
            }
            if (full3) {
                uint32_t Al[2][4], Bl[8][2];
#pragma unroll
                for (int mt = 0; mt < 2; mt++)
                    LDSM4(Al[mt][0], Al[mt][1], Al[mt][2], Al[mt][3],
                          smem_u32(sAl + aOff + mt * 640 + kh * 16));
#pragma unroll
                for (int nt2 = 0; nt2 < 4; nt2++) {
                    uint32_t b00, b01, b10, b11;
                    LDSM4(b00, b01, b10, b11, smem_u32(sBl + bOff + nt2 * 640 + kh * 16));
                    Bl[2 * nt2][0] = b00; Bl[2 * nt2][1] = b01;
                    Bl[2 * nt2 + 1][0] = b10; Bl[2 * nt2 + 1][1] = b11;
                }
#pragma unroll
                for (int mt = 0; mt < 2; mt++)
#pragma unroll
                    for (int nt = 0; nt < 8; nt++) {
                        mma16816(acc[mt][nt], Ah[mt][0], Ah[mt][1], Ah[mt][2], Ah[mt][3], Bh[nt][0], Bh[nt][1]);
                        mma16816(acc[mt][nt], Ah[mt][0], Ah[mt][1], Ah[mt][2], Ah[mt][3], Bl[nt][0], Bl[nt][1]);
                        mma16816(acc[mt][nt], Al[mt][0], Al[mt][1], Al[mt][2], Al[mt][3], Bh[nt][0], Bh[nt][1]);
                    }
            } else {
#pragma unroll
                for (int mt = 0; mt < 2; mt++)
#pragma unroll
                    for (int nt = 0; nt < 8; nt++)
                        mma16816(acc[mt][nt], Ah[mt][0], Ah[mt][1], Ah[mt][2], Ah[mt][3], Bh[nt][0], Bh[nt][1]);
            }
        }
    }

    if (bx < 4) {
#pragma unroll
        for (int mt = 0; mt < 2; mt++) {
            int r0 = m0 + wm * 32 + mt * 16 + (lane >> 2);
#pragma unroll
            for (int nt = 0; nt < 8; nt++) {
                int colg = n0 + wn * 64 + nt * 8 + (lane & 3) * 2;
                float b0 = g_bbig[colg], b1 = g_bbig[colg + 1];
                if (bx < 2) {
                    *(float2*)(g_h + r0 * 256 + colg) = make_float2(acc[mt][nt][0] + b0, acc[mt][nt][1] + b1);
                    *(float2*)(g_h + (r0 + 8) * 256 + colg) = make_float2(acc[mt][nt][2] + b0, acc[mt][nt][3] + b1);
                } else {
                    int cc = colg - 256;
                    *(bf162*)(g_vb + r0 * 256 + cc) = __floats2bfloat162_rn(acc[mt][nt][0] + b0, acc[mt][nt][1] + b1);
                    *(bf162*)(g_vb + (r0 + 8) * 256 + cc) = __floats2bfloat162_rn(acc[mt][nt][2] + b0, acc[mt][nt][3] + b1);
                }
            }
        }
    } else {
        // pair-grouped layout: per thread 8 consecutive p-pairs -> two uint4 per row
        int base = n0 - 512 + wn * 64;       // 0..448
        int arr = base >> 8;
        int p0 = (base >> 3) & 31;
#pragma unroll
        for (int mt = 0; mt < 2; mt++) {
            int r0 = m0 + wm * 32 + mt * 16 + (lane >> 2);
            uint32_t u0[8], u1[8];
#pragma unroll
            for (int nt = 0; nt < 8; nt++) {
                u0[nt] = pack_bf16(acc[mt][nt][0], acc[mt][nt][1]);
                u1[nt] = pack_bf16(acc[mt][nt][2], acc[mt][nt][3]);
            }
            bf16* d0 = g_nodeqk + (size_t)r0 * 512 + arr * 256 + (lane & 3) * 64 + p0 * 2;
            bf16* d1 = g_nodeqk + (size_t)(r0 + 8) * 512 + arr * 256 + (lane & 3) * 64 + p0 * 2;
            *(uint4*)d0       = make_uint4(u0[0], u0[1], u0[2], u0[3]);
            *(uint4*)(d0 + 8) = make_uint4(u0[4], u0[5], u0[6], u0[7]);
            *(uint4*)d1       = make_uint4(u1[0], u1[1], u1[2], u1[3]);
            *(uint4*)(d1 + 8) = make_uint4(u1[4], u1[5], u1[6], u1[7]);
        }
    }
}

// ---------------- fused edge kernel (mma.sync + ldmatrix + max + hist) -----
#define E_SEF   0
#define E_SWT   18432
#define E_SA2T  55296
#define E_SC    59520
#define E_SA2   60544
#define E_SSRC  60576
#define E_STGT  61088
#define EDGE_SMEM 61600

__global__ void __launch_bounds__(256) k_edge(const float* __restrict__ EF,
                                              const void* __restrict__ EI,
                                              const float* __restrict__ a2) {
    extern __shared__ char smE[];
    bf16*  sEF  = (bf16*)(smE + E_SEF);     // [128][72]
    bf16*  sWT  = (bf16*)(smE + E_SWT);     // [256][72]
    bf16*  sA2T = (bf16*)(smE + E_SA2T);    // [8][264]
    float* sc   = (float*)(smE + E_SC);
    float* sa2  = (float*)(smE + E_SA2);
    int*   ssrc = (int*)(smE + E_SSRC);
    int*   stgt = (int*)(smE + E_STGT);

    const int tid = threadIdx.x;
    const int lane = tid & 31, wid = tid >> 5;
    const int e0base = blockIdx.x * 128;
    const int is64 = g_is64;

#pragma unroll
    for (int j = 0; j < 8; j++) {
        int id = j * 256 + tid;
        int row = id >> 4, seg = id & 15;
        float4 v = *(const float4*)(EF + ((size_t)(e0base + row)) * 64 + seg * 4);
        bf162 p0 = __floats2bfloat162_rn(v.x, v.y);
        bf162 p1 = __floats2bfloat162_rn(v.z, v.w);
        uint2 u; u.x = *(uint32_t*)&p0; u.y = *(uint32_t*)&p1;
        *(uint2*)(sEF + row * 72 + seg * 4) = u;
    }
#pragma unroll
    for (int j = 0; j < 8; j++) {
        int id = j * 256 + tid;
        int row = id >> 3, seg = id & 7;
        uint4 v = *(const uint4*)(g_WeATb + row * 64 + seg * 8);
        *(uint4*)(sWT + row * 72 + seg * 8) = v;
    }
    {   // A2T: full coverage — 256 threads x 8 elements = 2048
        int row = tid >> 5, seg = tid & 31;
        uint4 v = *(const uint4*)(g_A2Tb + row * 256 + seg * 8);
        *(uint4*)(sA2T + row * 264 + seg * 8) = v;
    }
    sc[tid] = g_cvec[tid];
    if (tid < 8) sa2[tid] = a2[tid];
    if (tid < 128) {
        int sn = ld_idx(EI, e0base + tid, is64);
        ssrc[tid] = sn;
        stgt[tid] = ld_idx(EI, N_EDGES + e0base + tid, is64);
        atomicAdd(&g_deg[sn], 1);        // fused histogram
    }
    __syncthreads();

    // A fragments for this warp's 16 edges via ldmatrix
    const int tile = lane >> 3, tin = lane & 7;
    const int aOffE = (wid * 16 + (tile & 1) * 8 + tin) * 72 + (tile >> 1) * 8;
    const int bOffE = ((tile >> 1) * 8 + tin) * 72 + (tile & 1) * 8;
    uint32_t Af[4][4];
#pragma unroll
    for (int kh = 0; kh < 4; kh++)
        LDSM4(Af[kh][0], Af[kh][1], Af[kh][2], Af[kh][3], smem_u32(sEF + aOffE + kh * 16));

    const int sn0 = ssrc[wid * 16 + (lane >> 2)];
    const int sn1 = ssrc[wid * 16 + (lane >> 2) + 8];
    const int tn0 = stgt[wid * 16 + (lane >> 2)];
    const int tn1 = stgt[wid * 16 + (lane >> 2) + 8];
    const int j4 = lane & 3;

    float hacc[4] = {0.f, 0.f, 0.f, 0.f};

#pragma unroll
    for (int q4 = 0; q4 < 4; q4++) {
        // prefetch q/k gathers: 32B contiguous per lane per array (sector-perfect)
        uint4 qv[2][2], kv[2][2];
#pragma unroll
        for (int i = 0; i < 2; i++) {
            int sn = i ? sn1 : sn0;
            int tn = i ? tn1 : tn0;
            const bf16* qb = g_nodeqk + (size_t)sn * 512 + j4 * 64 + q4 * 16;
            const bf16* kb = g_nodeqk + (size_t)tn * 512 + 256 + j4 * 64 + q4 * 16;
            qv[i][0] = *(const uint4*)qb; qv[i][1] = *(const uint4*)(qb + 8);
            kv[i][0] = *(const uint4*)kb; kv[i][1] = *(const uint4*)(kb + 8);
        }

        float acc[8][4];
#pragma unroll
        for (int nt = 0; nt < 8; nt++)
#pragma unroll
            for (int c = 0; c < 4; c++) acc[nt][c] = 0.f;

#pragma unroll
        for (int kh = 0; kh < 4; kh++) {
            uint32_t B[8][2];
#pragma unroll
            for (int nt2 = 0; nt2 < 4; nt2++) {
                uint32_t b00, b01, b10, b11;
                LDSM4(b00, b01, b10, b11,
                      smem_u32(sWT + (q4 * 64 + nt2 * 16) * 72 + bOffE + kh * 16));
                B[2 * nt2][0] = b00; B[2 * nt2][1] = b01;
                B[2 * nt2 + 1][0] = b10; B[2 * nt2 + 1][1] = b11;
            }
#pragma unroll
            for (int nt = 0; nt < 8; nt++)
                mma16816(acc[nt], Af[kh][0], Af[kh][1], Af[kh][2], Af[kh][3], B[nt][0], B[nt][1]);
        }

        uint32_t zbuf[4][4];
#pragma unroll
        for (int nt = 0; nt < 8; nt++) {
            int colbase = q4 * 64 + nt * 8 + j4 * 2;
            float cc0 = sc[colbase], cc1 = sc[colbase + 1];
            int tt = nt >> 1;
#pragma unroll
            for (int i = 0; i < 2; i++) {
                bf162 qp = ((const bf162*)qv[i])[nt];
                bf162 kp = ((const bf162*)kv[i])[nt];
                float z0 = lrelu(acc[nt][2 * i]     + __bfloat162float(qp.x) + __bfloat162float(kp.x) + cc0);
                float z1 = lrelu(acc[nt][2 * i + 1] + __bfloat162float(qp.y) + __bfloat162float(kp.y) + cc1);
                zbuf[tt][(nt & 1) * 2 + i] = pack_bf16(z0, z1);
            }
        }

#pragma unroll
        for (int tt = 0; tt < 4; tt++) {
            int kcol = q4 * 64 + tt * 16 + j4 * 2;
            uint32_t b0 = *(const uint32_t*)(sA2T + (lane >> 2) * 264 + kcol);
            uint32_t b1 = *(const uint32_t*)(sA2T + (lane >> 2) * 264 + kcol + 8);
            mma16816(hacc, zbuf[tt][0], zbuf[tt][1], zbuf[tt][2], zbuf[tt][3], b0, b1);
        }
    }

    float a20 = sa2[j4 * 2], a21 = sa2[j4 * 2 + 1];
    float s0 = lrelu(hacc[0] + a20) + lrelu(hacc[1] + a21);
    float s1 = lrelu(hacc[2] + a20) + lrelu(hacc[3] + a21);
    s0 += __shfl_xor_sync(0xffffffffu, s0, 1);
    s0 += __shfl_xor_sync(0xffffffffu, s0, 2);
    s1 += __shfl_xor_sync(0xffffffffu, s1, 1);
    s1 += __shfl_xor_sync(0xffffffffu, s1, 2);
    if ((lane & 3) == 0) {
        int eg = e0base + wid * 16 + (lane >> 2);
        g_s[eg] = s0 * 0.125f;
        g_s[eg + 8] = s1 * 0.125f;
    }
    // fused block max -> atomicMax
    float mval = fmaxf(s0, s1) * 0.125f;
#pragma unroll
    for (int off = 4; off < 32; off <<= 1)
        mval = fmaxf(mval, __shfl_xor_sync(0xffffffffu, mval, off));
    __shared__ float swm[8];
    if (lane == 0) swm[wid] = mval;
    __syncthreads();
    if (tid == 0) {
        float m = swm[0];
#pragma unroll
        for (int i = 1; i < 8; i++) m = fmaxf(m, swm[i]);
        atomicMax(&g_smax_u, f2u_ord(m));
    }
}

// ---------------- counting sort scan ----------------
__global__ void k_scan() {
    int tid = threadIdx.x;
    int x[16];
    int base = tid * 16;
    int tot = 0;
#pragma unroll
    for (int i = 0; i < 16; i++) { x[i] = g_deg[base + i]; tot += x[i]; }
    int v = tot;
#pragma unroll
    for (int off = 1; off < 32; off <<= 1) {
        int t = __shfl_up_sync(0xffffffffu, v, off);
        if ((tid & 31) >= off) v += t;
    }
    __shared__ int sw[32];
    if ((tid & 31) == 31) sw[tid >> 5] = v;
    __syncthreads();
    if (tid < 32) {
        int t = sw[tid];
        int v2 = t;
#pragma unroll
        for (int off = 1; off < 32; off <<= 1) {
            int u = __shfl_up_sync(0xffffffffu, v2, off);
            if (tid >= off) v2 += u;
        }
        sw[tid] = v2 - t;
    }
    __syncthreads();
    int run = sw[tid >> 5] + v - tot;
#pragma unroll
    for (int i = 0; i < 16; i++) { g_off[base + i] = run; run += x[i]; }
    if (tid == 1023) g_off[N_NODES] = run;
}

// ---------------- place + exp-sum fused ----------------
__global__ void k_place_ssum(const void* __restrict__ EI) {
    int e = blockIdx.x * blockDim.x + threadIdx.x;
    int is64 = g_is64;
    float mx = u2f_ord(g_smax_u);
    float s = 0.f;
    if (e < N_EDGES) {
        int sn = ld_idx(EI, e, is64);
        int p = atomicAdd(&g_cur[sn], 1);
        g_eidx[g_off[sn] + p] = e;
        s = expf(g_s[e] - mx);
    }
#pragma unroll
    for (int off = 16; off; off >>= 1) s += __shfl_xor_sync(0xffffffffu, s, off);
    __shared__ float sm[8];
    if ((threadIdx.x & 31) == 0) sm[threadIdx.x >> 5] = s;
    __syncthreads();
    if (threadIdx.x == 0) {
        for (int i = 1; i < 8; i++) s += sm[i];
        atomicAdd(&g_ssum, s);
    }
}

// ---------------- final: weights + gather w*v[tgt] (bf162), add h, LayerNorm --
// 128 threads, 2 dims per thread (bf162 loads halve LDG count).
__global__ void __launch_bounds__(128) k_final(const void* __restrict__ EI,
                                               const float* __restrict__ gamma,
                                               const float* __restrict__ beta,
                                               float* __restrict__ out) {
    int n = blockIdx.x;
    int t = threadIdx.x;
    int is64 = g_is64;
    float mx = u2f_ord(g_smax_u);
    float rinv = 1.f / g_ssum;
    float2 acc = *(const float2*)(g_h + n * 256 + t * 2);
    int beg = g_off[n], end = g_off[n + 1];

    __shared__ float swv[128];
    __shared__ int stg[128];
    for (int chunk = beg; chunk < end; chunk += 128) {
        int m = min(128, end - chunk);
        if (t < m) {
            int e = g_eidx[chunk + t];
            swv[t] = expf(g_s[e] - mx) * rinv;
            stg[t] = ld_idx(EI, N_EDGES + e, is64);
        }
        __syncthreads();
        for (int i = 0; i < m; i++) {
            float w = swv[i];
            bf162 vv = *(const bf162*)(g_vb + (size_t)stg[i] * 256 + t * 2);
            acc.x += w * __bfloat162float(vv.x);
            acc.y += w * __bfloat162float(vv.y);
        }
        __syncthreads();
    }

    float v1 = acc.x + acc.y, v2 = acc.x * acc.x + acc.y * acc.y;
#pragma unroll
    for (int off = 16; off; off >>= 1) {
        v1 += __shfl_xor_sync(0xffffffffu, v1, off);
        v2 += __shfl_xor_sync(0xffffffffu, v2, off);
    }
    __shared__ float s1[4], s2[4];
    __shared__ float s_mu, s_rstd;
    int wid = t >> 5, lane = t & 31;
    if (lane == 0) { s1[wid] = v1; s2[wid] = v2; }
    __syncthreads();
    if (t == 0) {
        float S = 0.f, Q = 0.f;
        for (int i = 0; i < 4; i++) { S += s1[i]; Q += s2[i]; }
        float mu = S * (1.f / 256.f);
        float var = Q * (1.f / 256.f) - mu * mu;
        s_mu = mu;
        s_rstd = rsqrtf(var + 1e-5f);
    }
    __syncthreads();
    float g0 = gamma[t * 2], g1 = gamma[t * 2 + 1];
    float be0 = beta[t * 2], be1 = beta[t * 2 + 1];
    *(float2*)(out + n * 256 + t * 2) =
        make_float2((acc.x - s_mu) * s_rstd * g0 + be0,
                    (acc.y - s_mu) * s_rstd * g1 + be1);
}

// ---------------- launch ----------------
extern "C" void kernel_launch(void* const* d_in, const int* in_sizes, int n_in,
                              void* d_out, int out_size) {
    const float* X     = (const float*)d_in[0];
    const void*  EI    = d_in[1];
    const float* EF    = (const float*)d_in[2];
    const float* Wn    = (const float*)d_in[3];
    const float* bn    = (const float*)d_in[4];
    const float* Wq    = (const float*)d_in[5];
    const float* bq    = (const float*)d_in[6];
    const float* Wk    = (const float*)d_in[7];
    const float* bk    = (const float*)d_in[8];
    const float* Wv    = (const float*)d_in[9];
    const float* bv    = (const float*)d_in[10];
    const float* We    = (const float*)d_in[11];
    const float* be    = (const float*)d_in[12];
    const float* A1    = (const float*)d_in[13];
    const float* a1    = (const float*)d_in[14];
    const float* A2    = (const float*)d_in[15];
    const float* a2    = (const float*)d_in[16];
    const float* gamma = (const float*)d_in[17];
    const float* beta  = (const float*)d_in[18];
    float* out = (float*)d_out;

    cudaFuncSetAttribute(k_node_gemm, cudaFuncAttributeMaxDynamicSharedMemorySize, NGM_SMEM);
    cudaFuncSetAttribute(k_edge, cudaFuncAttributeMaxDynamicSharedMemorySize, EDGE_SMEM);

    k_pre<<<4096, 256>>>(EI, Wn, bn, Wv, bv, A2, X);
    k_prep_fold<<<145, 256>>>(Wq, bq, Wk, bk, We, be, A1, a1);
    k_node_gemm<<<dim3(8, 128), 256, NGM_SMEM>>>();
    k_edge<<<2048, 256, EDGE_SMEM>>>(EF, EI, a2);     // launch #4 -> profiled
    k_scan<<<1, 1024>>>();
    k_place_ssum<<<1024, 256>>>(EI);
    k_final<<<16384, 128>>>(EI, gamma, beta, out);
}

// round 10
// speedup vs baseline: 3.4122x; 1.2344x over previous
#include <cuda_runtime.h>
#include <cuda_bf16.h>
#include <math.h>
#include <stdint.h>

#define N_NODES 16384
#define N_EDGES 262144
#define DN 256
#define DE 64
#define NH 8

typedef __nv_bfloat16 bf16;
typedef __nv_bfloat162 bf162;

// ---------------- device scratch (static allocations only) ----------------
__device__ bf16  g_WThi[1024 * 256];           // W^T [n][k]: Wn|Wv|WqA1q|WkA1k (hi)
__device__ bf16  g_WTlo[1024 * 256];           // lo (only n<512 written/used)
__device__ float g_bbig[512];                  // bn | bv
__device__ bf16  g_Xhi[N_NODES * 256];
__device__ bf16  g_Xlo[N_NODES * 256];
__device__ bf16  g_WeATb[256 * 64];            // (We@A1e)^T [n=256][k=64] bf16
__device__ float g_cvec[DN];                   // bq@A1q + bk@A1k + be@A1e + a1
__device__ bf16  g_A2Tb[8 * 256];              // A2^T [h][d] bf16
__device__ float g_h[N_NODES * 256];           // h (fp32)
__device__ bf16  g_vb[N_NODES * 256];          // v (bf16)
// Pq|Pk per node, LINE-GROUPED layout: [node][arr(q=0,k=1)][q4=0..3][j4=0..3][p=0..7]
// element offset of original col c: arr*256 + (c>>6)*64 + ((c>>1)&3)*16 + ((c&63)>>3)*2 + (c&1)
// -> per (edge, arr, q4) all four j4 lanes read within ONE 128B-aligned line.
__device__ bf16  g_nodeqk[N_NODES * 512];
__device__ float g_s[N_EDGES];                 // per-edge pre-softmax score
__device__ int   g_deg[N_NODES];
__device__ int   g_off[N_NODES + 1];
__device__ int   g_cur[N_NODES];
__device__ int   g_eidx[N_EDGES];
__device__ unsigned int g_smax_u;
__device__ float g_ssum;
__device__ int   g_is64;

__device__ __forceinline__ float lrelu(float x) { return x > 0.f ? x : 0.2f * x; }

__device__ __forceinline__ int ld_idx(const void* EI, int pos, int is64) {
    if (is64) return (int)((const long long*)EI)[pos];
    return ((const int*)EI)[pos];
}

__device__ __forceinline__ uint32_t pack_bf16(float x, float y) {
    bf162 p = __floats2bfloat162_rn(x, y);
    return *reinterpret_cast<uint32_t*>(&p);
}

__device__ __forceinline__ void mma16816(float* d, uint32_t a0, uint32_t a1, uint32_t a2, uint32_t a3,
                                         uint32_t b0, uint32_t b1) {
    asm volatile(
        "mma.sync.aligned.m16n8k16.row.col.f32.bf16.bf16.f32 "
        "{%0,%1,%2,%3},{%4,%5,%6,%7},{%8,%9},{%0,%1,%2,%3};"
        : "+f"(d[0]), "+f"(d[1]), "+f"(d[2]), "+f"(d[3])
        : "r"(a0), "r"(a1), "r"(a2), "r"(a3), "r"(b0), "r"(b1));
}

__device__ __forceinline__ uint32_t smem_u32(const void* p) {
    return (uint32_t)__cvta_generic_to_shared(p);
}
#define CP16(dst, src) asm volatile("cp.async.ca.shared.global [%0], [%1], 16;\n" :: "r"(dst), "l"(src))
#define LDSM4(r0, r1, r2, r3, addr) \
    asm volatile("ldmatrix.sync.aligned.m8n8.x4.shared.b16 {%0,%1,%2,%3}, [%4];" \
                 : "=r"(r0), "=r"(r1), "=r"(r2), "=r"(r3) : "r"(addr))

__device__ __forceinline__ unsigned f2u_ord(float f) {
    unsigned u = __float_as_uint(f);
    return (u & 0x80000000u) ? ~u : (u | 0x80000000u);
}
__device__ __forceinline__ float u2f_ord(unsigned u) {
    return (u & 0x80000000u) ? __uint_as_float(u ^ 0x80000000u) : __uint_as_float(~u);
}

// ---------------- k_pre: dtype detect + init + Wn/Wv transpose-split + A2T + convX --
__global__ void k_pre(const void* EI, const float* __restrict__ Wn, const float* __restrict__ bn,
                      const float* __restrict__ Wv, const float* __restrict__ bv,
                      const float* __restrict__ A2, const float* __restrict__ X) {
    int gtid = blockIdx.x * blockDim.x + threadIdx.x;
    // ---- convX: all 1048576 float4s ----
    {
        float4 v = ((const float4*)X)[gtid];
        bf162 h0 = __floats2bfloat162_rn(v.x, v.y);
        bf162 h1 = __floats2bfloat162_rn(v.z, v.w);
        bf162 l0 = __floats2bfloat162_rn(v.x - __bfloat162float(h0.x), v.y - __bfloat162float(h0.y));
        bf162 l1 = __floats2bfloat162_rn(v.z - __bfloat162float(h1.x), v.w - __bfloat162float(h1.y));
        uint2 uh, ul;
        uh.x = *(uint32_t*)&h0; uh.y = *(uint32_t*)&h1;
        ul.x = *(uint32_t*)&l0; ul.y = *(uint32_t*)&l1;
        ((uint2*)g_Xhi)[gtid] = uh;
        ((uint2*)g_Xlo)[gtid] = ul;
    }
    if (gtid >= 131072) return;
    if (blockIdx.x == 0) {
        __shared__ int bad;
        if (threadIdx.x == 0) bad = 0;
        __syncthreads();
        long long v = ((const long long*)EI)[threadIdx.x];
        if (v < 0 || v >= N_NODES) atomicOr(&bad, 1);
        __syncthreads();
        if (threadIdx.x == 0) g_is64 = bad ? 0 : 1;
    }
    {   // Wn|Wv -> transposed hi/lo  (k row, j col of 512)
        int k = gtid >> 9, j = gtid & 511;
        float w = (j < 256) ? Wn[k * 256 + j] : Wv[k * 256 + j - 256];
        bf16 hi = __float2bfloat16_rn(w);
        g_WThi[j * 256 + k] = hi;
        g_WTlo[j * 256 + k] = __float2bfloat16_rn(w - __bfloat162float(hi));
    }
    if (gtid < N_NODES) { g_deg[gtid] = 0; g_cur[gtid] = 0; }
    if (gtid < 512) g_bbig[gtid] = (gtid < 256) ? bn[gtid] : bv[gtid - 256];
    if (gtid < 2048) { int h = gtid >> 8, d = gtid & 255; g_A2Tb[gtid] = __float2bfloat16_rn(A2[d * 8 + h]); }
    if (gtid == 0) { g_smax_u = 0u; g_ssum = 0.f; }
}

// ---------------- k_prep_fold: tiled GEMMs WqA/WkA/WeA + cvec --------------
__global__ void __launch_bounds__(256) k_prep_fold(const float* __restrict__ Wq, const float* __restrict__ bq,
                                                   const float* __restrict__ Wk, const float* __restrict__ bk,
                                                   const float* __restrict__ We, const float* __restrict__ be,
                                                   const float* __restrict__ A1, const float* __restrict__ a1) {
    int bid = blockIdx.x;
    int tid = threadIdx.x;
    if (bid == 144) {   // cvec
        int j = tid;
        float s = a1[j];
#pragma unroll 4
        for (int m = 0; m < 256; m++) {
            s += bq[m] * A1[m * 256 + j];
            s += bk[m] * A1[(256 + m) * 256 + j];
            s += be[m] * A1[(512 + m) * 256 + j];
        }
        g_cvec[j] = s;
        return;
    }
    int z, kt, jt, zoff;
    const float* W;
    if (bid < 64)       { z = 0; W = Wq; zoff = 0;   int t = bid;       kt = t >> 3; jt = t & 7; }
    else if (bid < 128) { z = 1; W = Wk; zoff = 256; int t = bid - 64;  kt = t >> 3; jt = t & 7; }
    else                { z = 2; W = We; zoff = 512; int t = bid - 128; kt = t >> 3; jt = t & 7; }
    int k0 = kt * 32, j0 = jt * 32;
    __shared__ float Ws[32][33], As[32][33];
    int ty = tid >> 4, tx = tid & 15;
    float acc[2][2] = {{0.f, 0.f}, {0.f, 0.f}};
    for (int m0 = 0; m0 < 256; m0 += 32) {
#pragma unroll
        for (int i = 0; i < 4; i++) {
            int id = i * 256 + tid;
            int r = id >> 5, c = id & 31;
            Ws[r][c] = W[(k0 + r) * 256 + m0 + c];
            As[r][c] = A1[(zoff + m0 + r) * 256 + j0 + c];
        }
        __syncthreads();
#pragma unroll 8
        for (int m = 0; m < 32; m++) {
            float a0 = Ws[ty * 2][m], a1v = Ws[ty * 2 + 1][m];
            float b0 = As[m][tx * 2], b1 = As[m][tx * 2 + 1];
            acc[0][0] += a0 * b0; acc[0][1] += a0 * b1;
            acc[1][0] += a1v * b0; acc[1][1] += a1v * b1;
        }
        __syncthreads();
    }
#pragma unroll
    for (int i = 0; i < 2; i++)
#pragma unroll
        for (int j = 0; j < 2; j++) {
            int k = k0 + ty * 2 + i, jg = j0 + tx * 2 + j;
            if (z < 2) g_WThi[(512 + z * 256 + jg) * 256 + k] = __float2bfloat16_rn(acc[i][j]);
            else       g_WeATb[jg * 64 + k] = __float2bfloat16_rn(acc[i][j]);
        }
}

// ---------------- node GEMM: [16384,256] @ [256,1024], mma.sync + ldmatrix --
#define NGM_SMEM (2 * 4 * 128 * 40 * 2)   // 81920 bytes

__global__ void __launch_bounds__(256) k_node_gemm() {
    extern __shared__ bf16 smN[];
    const int tid = threadIdx.x;
    const int lane = tid & 31, wid = tid >> 5;
    const int wm = wid & 3, wn = wid >> 2;
    const int bx = blockIdx.x;
    const int m0 = blockIdx.y * 128, n0 = bx * 128;
    const bool full3 = (bx < 2);

    const int tile = lane >> 3, tin = lane & 7;
    const int aOff = (wm * 32 + (tile & 1) * 8 + tin) * 40 + (tile >> 1) * 8;
    const int bOff = (wn * 64 + (tile >> 1) * 8 + tin) * 40 + (tile & 1) * 8;

    float acc[2][8][4];
#pragma unroll
    for (int mt = 0; mt < 2; mt++)
#pragma unroll
        for (int nt = 0; nt < 8; nt++)
#pragma unroll
            for (int c = 0; c < 4; c++) acc[mt][nt][c] = 0.f;

    auto load_chunk = [&](int c, int buf) {
        int k0 = c * 32;
        if (full3) {
#pragma unroll
            for (int j = 0; j < 8; j++) {
                int id = j * 256 + tid;
                int arr = id >> 9;
                int rem = id & 511;
                int row = rem >> 2, seg = rem & 3;
                const bf16* src;
                if (arr == 0)      src = g_Xhi  + (m0 + row) * 256 + k0 + seg * 8;
                else if (arr == 1) src = g_Xlo  + (m0 + row) * 256 + k0 + seg * 8;
                else if (arr == 2) src = g_WThi + (n0 + row) * 256 + k0 + seg * 8;
                else               src = g_WTlo + (n0 + row) * 256 + k0 + seg * 8;
                uint32_t dst = smem_u32(smN + buf * 20480 + arr * 5120 + row * 40 + seg * 8);
                CP16(dst, src);
            }
        } else {
#pragma unroll
            for (int j = 0; j < 4; j++) {
                int id = j * 256 + tid;
                int sel = id >> 9;
                int rem = id & 511;
                int row = rem >> 2, seg = rem & 3;
                const bf16* src = (sel == 0) ? g_Xhi + (m0 + row) * 256 + k0 + seg * 8
                                             : g_WThi + (n0 + row) * 256 + k0 + seg * 8;
                uint32_t dst = smem_u32(smN + buf * 20480 + (sel * 2) * 5120 + row * 40 + seg * 8);
                CP16(dst, src);
            }
        }
        asm volatile("cp.async.commit_group;\n" ::);
    };

    load_chunk(0, 0);

    for (int c = 0; c < 8; c++) {
        asm volatile("cp.async.wait_group 0;\n" ::);
        __syncthreads();
        if (c < 7) load_chunk(c + 1, (c + 1) & 1);

        const int bb = (c & 1) * 20480;
        const bf16* sAh = smN + bb;
        const bf16* sAl = smN + bb + 5120;
        const bf16* sBh = smN + bb + 2 * 5120;
        const bf16* sBl = smN + bb + 3 * 5120;

#pragma unroll
        for (int kh = 0; kh < 2; kh++) {
            uint32_t Ah[2][4], Bh[8][2];
#pragma unroll
            for (int mt = 0; mt < 2; mt++)
                LDSM4(Ah[mt][0], Ah[mt][1], Ah[mt][2], Ah[mt][3],
                      smem_u32(sAh + aOff + mt * 640 + kh * 16));
#pragma unroll
            for (int nt2 = 0; nt2 < 4; nt2++) {
                uint32_t b00, b01, b10, b11;
                LDSM4(b00, b01, b10, b11, smem_u32(sBh + bOff + nt2 * 640 + kh * 16));
                Bh[2 * nt2][0] = b00; Bh[2 * nt2][1] = b01;
                Bh[2 * nt2 + 1][0] = b10; Bh[2 * nt2 + 1][1] = b11;
            }
            if (full3) {
                uint32_t Al[2][4], Bl[8][2];
#pragma unroll
                for (int mt = 0; mt < 2; mt++)
                    LDSM4(Al[mt][0], Al[mt][1], Al[mt][2], Al[mt][3],
                          smem_u32(sAl + aOff + mt * 640 + kh * 16));
#pragma unroll
                for (int nt2 = 0; nt2 < 4; nt2++) {
                    uint32_t b00, b01, b10, b11;
                    LDSM4(b00, b01, b10, b11, smem_u32(sBl + bOff + nt2 * 640 + kh * 16));
                    Bl[2 * nt2][0] = b00; Bl[2 * nt2][1] = b01;
                    Bl[2 * nt2 + 1][0] = b10; Bl[2 * nt2 + 1][1] = b11;
                }
#pragma unroll
                for (int mt = 0; mt < 2; mt++)
#pragma unroll
                    for (int nt = 0; nt < 8; nt++) {
                        mma16816(acc[mt][nt], Ah[mt][0], Ah[mt][1], Ah[mt][2], Ah[mt][3], Bh[nt][0], Bh[nt][1]);
                        mma16816(acc[mt][nt], Ah[mt][0], Ah[mt][1], Ah[mt][2], Ah[mt][3], Bl[nt][0], Bl[nt][1]);
                        mma16816(acc[mt][nt], Al[mt][0], Al[mt][1], Al[mt][2], Al[mt][3], Bh[nt][0], Bh[nt][1]);
                    }
            } else {
#pragma unroll
                for (int mt = 0; mt < 2; mt++)
#pragma unroll
                    for (int nt = 0; nt < 8; nt++)
                        mma16816(acc[mt][nt], Ah[mt][0], Ah[mt][1], Ah[mt][2], Ah[mt][3], Bh[nt][0], Bh[nt][1]);
            }
        }
    }

    if (bx < 4) {
#pragma unroll
        for (int mt = 0; mt < 2; mt++) {
            int r0 = m0 + wm * 32 + mt * 16 + (lane >> 2);
#pragma unroll
            for (int nt = 0; nt < 8; nt++) {
                int colg = n0 + wn * 64 + nt * 8 + (lane & 3) * 2;
                float b0 = g_bbig[colg], b1 = g_bbig[colg + 1];
                if (bx < 2) {
                    *(float2*)(g_h + r0 * 256 + colg) = make_float2(acc[mt][nt][0] + b0, acc[mt][nt][1] + b1);
                    *(float2*)(g_h + (r0 + 8) * 256 + colg) = make_float2(acc[mt][nt][2] + b0, acc[mt][nt][3] + b1);
                } else {
                    int cc = colg - 256;
                    *(bf162*)(g_vb + r0 * 256 + cc) = __floats2bfloat162_rn(acc[mt][nt][0] + b0, acc[mt][nt][1] + b1);
                    *(bf162*)(g_vb + (r0 + 8) * 256 + cc) = __floats2bfloat162_rn(acc[mt][nt][2] + b0, acc[mt][nt][3] + b1);
                }
            }
        }
    } else {
        // line-grouped layout: [arr][q4][j4][p]; thread stores 16 consecutive
        // elements (pairs nt=0..7) at arr*256 + q4*64 + j4*16 -> two uint4s.
        int base = n0 - 512 + wn * 64;       // multiple of 64: 0..448
        int arr = base >> 8;
        int q4 = (base >> 6) & 3;
#pragma unroll
        for (int mt = 0; mt < 2; mt++) {
            int r0 = m0 + wm * 32 + mt * 16 + (lane >> 2);
            uint32_t u0[8], u1[8];
#pragma unroll
            for (int nt = 0; nt < 8; nt++) {
                u0[nt] = pack_bf16(acc[mt][nt][0], acc[mt][nt][1]);
                u1[nt] = pack_bf16(acc[mt][nt][2], acc[mt][nt][3]);
            }
            bf16* d0 = g_nodeqk + (size_t)r0 * 512 + arr * 256 + q4 * 64 + (lane & 3) * 16;
            bf16* d1 = g_nodeqk + (size_t)(r0 + 8) * 512 + arr * 256 + q4 * 64 + (lane & 3) * 16;
            *(uint4*)d0       = make_uint4(u0[0], u0[1], u0[2], u0[3]);
            *(uint4*)(d0 + 8) = make_uint4(u0[4], u0[5], u0[6], u0[7]);
            *(uint4*)d1       = make_uint4(u1[0], u1[1], u1[2], u1[3]);
            *(uint4*)(d1 + 8) = make_uint4(u1[4], u1[5], u1[6], u1[7]);
        }
    }
}

// ---------------- fused edge kernel (mma.sync + ldmatrix + max + hist) -----
#define E_SEF   0
#define E_SWT   18432
#define E_SA2T  55296
#define E_SC    59520
#define E_SA2   60544
#define E_SSRC  60576
#define E_STGT  61088
#define EDGE_SMEM 61600

__global__ void __launch_bounds__(256) k_edge(const float* __restrict__ EF,
                                              const void* __restrict__ EI,
                                              const float* __restrict__ a2) {
    extern __shared__ char smE[];
    bf16*  sEF  = (bf16*)(smE + E_SEF);     // [128][72]
    bf16*  sWT  = (bf16*)(smE + E_SWT);     // [256][72]
    bf16*  sA2T = (bf16*)(smE + E_SA2T);    // [8][264]
    float* sc   = (float*)(smE + E_SC);
    float* sa2  = (float*)(smE + E_SA2);
    int*   ssrc = (int*)(smE + E_SSRC);
    int*   stgt = (int*)(smE + E_STGT);

    const int tid = threadIdx.x;
    const int lane = tid & 31, wid = tid >> 5;
    const int e0base = blockIdx.x * 128;
    const int is64 = g_is64;

#pragma unroll
    for (int j = 0; j < 8; j++) {
        int id = j * 256 + tid;
        int row = id >> 4, seg = id & 15;
        float4 v = *(const float4*)(EF + ((size_t)(e0base + row)) * 64 + seg * 4);
        bf162 p0 = __floats2bfloat162_rn(v.x, v.y);
        bf162 p1 = __floats2bfloat162_rn(v.z, v.w);
        uint2 u; u.x = *(uint32_t*)&p0; u.y = *(uint32_t*)&p1;
        *(uint2*)(sEF + row * 72 + seg * 4) = u;
    }
#pragma unroll
    for (int j = 0; j < 8; j++) {
        int id = j * 256 + tid;
        int row = id >> 3, seg = id & 7;
        uint4 v = *(const uint4*)(g_WeATb + row * 64 + seg * 8);
        *(uint4*)(sWT + row * 72 + seg * 8) = v;
    }
    {   // A2T: full coverage — 256 threads x 8 elements = 2048
        int row = tid >> 5, seg = tid & 31;
        uint4 v = *(const uint4*)(g_A2Tb + row * 256 + seg * 8);
        *(uint4*)(sA2T + row * 264 + seg * 8) = v;
    }
    sc[tid] = g_cvec[tid];
    if (tid < 8) sa2[tid] = a2[tid];
    if (tid < 128) {
        int sn = ld_idx(EI, e0base + tid, is64);
        ssrc[tid] = sn;
        stgt[tid] = ld_idx(EI, N_EDGES + e0base + tid, is64);
        atomicAdd(&g_deg[sn], 1);        // fused histogram
    }
    __syncthreads();

    // A fragments for this warp's 16 edges via ldmatrix
    const int tile = lane >> 3, tin = lane & 7;
    const int aOffE = (wid * 16 + (tile & 1) * 8 + tin) * 72 + (tile >> 1) * 8;
    const int bOffE = ((tile >> 1) * 8 + tin) * 72 + (tile & 1) * 8;
    uint32_t Af[4][4];
#pragma unroll
    for (int kh = 0; kh < 4; kh++)
        LDSM4(Af[kh][0], Af[kh][1], Af[kh][2], Af[kh][3], smem_u32(sEF + aOffE + kh * 16));

    const int sn0 = ssrc[wid * 16 + (lane >> 2)];
    const int sn1 = ssrc[wid * 16 + (lane >> 2) + 8];
    const int tn0 = stgt[wid * 16 + (lane >> 2)];
    const int tn1 = stgt[wid * 16 + (lane >> 2) + 8];
    const int j4 = lane & 3;

    float hacc[4] = {0.f, 0.f, 0.f, 0.f};

#pragma unroll
    for (int q4 = 0; q4 < 4; q4++) {
        // gather: line-grouped layout -> the 4 j4 lanes of an edge read one
        // 128B-aligned line (q4*128B within node); 8 lines per instruction.
        uint4 qv[2][2], kv[2][2];
#pragma unroll
        for (int i = 0; i < 2; i++) {
            int sn = i ? sn1 : sn0;
            int tn = i ? tn1 : tn0;
            const bf16* qb = g_nodeqk + (size_t)sn * 512 + q4 * 64 + j4 * 16;
            const bf16* kb = g_nodeqk + (size_t)tn * 512 + 256 + q4 * 64 + j4 * 16;
            qv[i][0] = *(const uint4*)qb; qv[i][1] = *(const uint4*)(qb + 8);
            kv[i][0] = *(const uint4*)kb; kv[i][1] = *(const uint4*)(kb + 8);
        }

        float acc[8][4];
#pragma unroll
        for (int nt = 0; nt < 8; nt++)
#pragma unroll
            for (int c = 0; c < 4; c++) acc[nt][c] = 0.f;

#pragma unroll
        for (int kh = 0; kh < 4; kh++) {
            uint32_t B[8][2];
#pragma unroll
            for (int nt2 = 0; nt2 < 4; nt2++) {
                uint32_t b00, b01, b10, b11;
                LDSM4(b00, b01, b10, b11,
                      smem_u32(sWT + (q4 * 64 + nt2 * 16) * 72 + bOffE + kh * 16));
                B[2 * nt2][0] = b00; B[2 * nt2][1] = b01;
                B[2 * nt2 + 1][0] = b10; B[2 * nt2 + 1][1] = b11;
            }
#pragma unroll
            for (int nt = 0; nt < 8; nt++)
                mma16816(acc[nt], Af[kh][0], Af[kh][1], Af[kh][2], Af[kh][3], B[nt][0], B[nt][1]);
        }

        uint32_t zbuf[4][4];
#pragma unroll
        for (int nt = 0; nt < 8; nt++) {
            int colbase = q4 * 64 + nt * 8 + j4 * 2;
            float cc0 = sc[colbase], cc1 = sc[colbase + 1];
            int tt = nt >> 1;
#pragma unroll
            for (int i = 0; i < 2; i++) {
                bf162 qp = ((const bf162*)qv[i])[nt];
                bf162 kp = ((const bf162*)kv[i])[nt];
                float z0 = lrelu(acc[nt][2 * i]     + __bfloat162float(qp.x) + __bfloat162float(kp.x) + cc0);
                float z1 = lrelu(acc[nt][2 * i + 1] + __bfloat162float(qp.y) + __bfloat162float(kp.y) + cc1);
                zbuf[tt][(nt & 1) * 2 + i] = pack_bf16(z0, z1);
            }
        }

#pragma unroll
        for (int tt = 0; tt < 4; tt++) {
            int kcol = q4 * 64 + tt * 16 + j4 * 2;
            uint32_t b0 = *(const uint32_t*)(sA2T + (lane >> 2) * 264 + kcol);
            uint32_t b1 = *(const uint32_t*)(sA2T + (lane >> 2) * 264 + kcol + 8);
            mma16816(hacc, zbuf[tt][0], zbuf[tt][1], zbuf[tt][2], zbuf[tt][3], b0, b1);
        }
    }

    float a20 = sa2[j4 * 2], a21 = sa2[j4 * 2 + 1];
    float s0 = lrelu(hacc[0] + a20) + lrelu(hacc[1] + a21);
    float s1 = lrelu(hacc[2] + a20) + lrelu(hacc[3] + a21);
    s0 += __shfl_xor_sync(0xffffffffu, s0, 1);
    s0 += __shfl_xor_sync(0xffffffffu, s0, 2);
    s1 += __shfl_xor_sync(0xffffffffu, s1, 1);
    s1 += __shfl_xor_sync(0xffffffffu, s1, 2);
    if ((lane & 3) == 0) {
        int eg = e0base + wid * 16 + (lane >> 2);
        g_s[eg] = s0 * 0.125f;
        g_s[eg + 8] = s1 * 0.125f;
    }
    // fused block max -> atomicMax
    float mval = fmaxf(s0, s1) * 0.125f;
#pragma unroll
    for (int off = 4; off < 32; off <<= 1)
        mval = fmaxf(mval, __shfl_xor_sync(0xffffffffu, mval, off));
    __shared__ float swm[8];
    if (lane == 0) swm[wid] = mval;
    __syncthreads();
    if (tid == 0) {
        float m = swm[0];
#pragma unroll
        for (int i = 1; i < 8; i++) m = fmaxf(m, swm[i]);
        atomicMax(&g_smax_u, f2u_ord(m));
    }
}

// ---------------- counting sort scan ----------------
__global__ void k_scan() {
    int tid = threadIdx.x;
    int x[16];
    int base = tid * 16;
    int tot = 0;
#pragma unroll
    for (int i = 0; i < 16; i++) { x[i] = g_deg[base + i]; tot += x[i]; }
    int v = tot;
#pragma unroll
    for (int off = 1; off < 32; off <<= 1) {
        int t = __shfl_up_sync(0xffffffffu, v, off);
        if ((tid & 31) >= off) v += t;
    }
    __shared__ int sw[32];
    if ((tid & 31) == 31) sw[tid >> 5] = v;
    __syncthreads();
    if (tid < 32) {
        int t = sw[tid];
        int v2 = t;
#pragma unroll
        for (int off = 1; off < 32; off <<= 1) {
            int u = __shfl_up_sync(0xffffffffu, v2, off);
            if (tid >= off) v2 += u;
        }
        sw[tid] = v2 - t;
    }
    __syncthreads();
    int run = sw[tid >> 5] + v - tot;
#pragma unroll
    for (int i = 0; i < 16; i++) { g_off[base + i] = run; run += x[i]; }
    if (tid == 1023) g_off[N_NODES] = run;
}

// ---------------- place + exp-sum fused ----------------
__global__ void k_place_ssum(const void* __restrict__ EI) {
    int e = blockIdx.x * blockDim.x + threadIdx.x;
    int is64 = g_is64;
    float mx = u2f_ord(g_smax_u);
    float s = 0.f;
    if (e < N_EDGES) {
        int sn = ld_idx(EI, e, is64);
        int p = atomicAdd(&g_cur[sn], 1);
        g_eidx[g_off[sn] + p] = e;
        s = expf(g_s[e] - mx);
    }
#pragma unroll
    for (int off = 16; off; off >>= 1) s += __shfl_xor_sync(0xffffffffu, s, off);
    __shared__ float sm[8];
    if ((threadIdx.x & 31) == 0) sm[threadIdx.x >> 5] = s;
    __syncthreads();
    if (threadIdx.x == 0) {
        for (int i = 1; i < 8; i++) s += sm[i];
        atomicAdd(&g_ssum, s);
    }
}

// ---------------- final: weights + gather w*v[tgt] (bf162), add h, LayerNorm --
__global__ void __launch_bounds__(128) k_final(const void* __restrict__ EI,
                                               const float* __restrict__ gamma,
                                               const float* __restrict__ beta,
                                               float* __restrict__ out) {
    int n = blockIdx.x;
    int t = threadIdx.x;
    int is64 = g_is64;
    float mx = u2f_ord(g_smax_u);
    float rinv = 1.f / g_ssum;
    float2 acc = *(const float2*)(g_h + n * 256 + t * 2);
    int beg = g_off[n], end = g_off[n + 1];

    __shared__ float swv[128];
    __shared__ int stg[128];
    for (int chunk = beg; chunk < end; chunk += 128) {
        int m = min(128, end - chunk);
        if (t < m) {
            int e = g_eidx[chunk + t];
            swv[t] = expf(g_s[e] - mx) * rinv;
            stg[t] = ld_idx(EI, N_EDGES + e, is64);
        }
        __syncthreads();
        for (int i = 0; i < m; i++) {
            float w = swv[i];
            bf162 vv = *(const bf162*)(g_vb + (size_t)stg[i] * 256 + t * 2);
            acc.x += w * __bfloat162float(vv.x);
            acc.y += w * __bfloat162float(vv.y);
        }
        __syncthreads();
    }

    float v1 = acc.x + acc.y, v2 = acc.x * acc.x + acc.y * acc.y;
#pragma unroll
    for (int off = 16; off; off >>= 1) {
        v1 += __shfl_xor_sync(0xffffffffu, v1, off);
        v2 += __shfl_xor_sync(0xffffffffu, v2, off);
    }
    __shared__ float s1[4], s2[4];
    __shared__ float s_mu, s_rstd;
    int wid = t >> 5, lane = t & 31;
    if (lane == 0) { s1[wid] = v1; s2[wid] = v2; }
    __syncthreads();
    if (t == 0) {
        float S = 0.f, Q = 0.f;
        for (int i = 0; i < 4; i++) { S += s1[i]; Q += s2[i]; }
        float mu = S * (1.f / 256.f);
        float var = Q * (1.f / 256.f) - mu * mu;
        s_mu = mu;
        s_rstd = rsqrtf(var + 1e-5f);
    }
    __syncthreads();
    float g0 = gamma[t * 2], g1 = gamma[t * 2 + 1];
    float be0 = beta[t * 2], be1 = beta[t * 2 + 1];
    *(float2*)(out + n * 256 + t * 2) =
        make_float2((acc.x - s_mu) * s_rstd * g0 + be0,
                    (acc.y - s_mu) * s_rstd * g1 + be1);
}

// ---------------- launch ----------------
extern "C" void kernel_launch(void* const* d_in, const int* in_sizes, int n_in,
                              void* d_out, int out_size) {
    const float* X     = (const float*)d_in[0];
    const void*  EI    = d_in[1];
    const float* EF    = (const float*)d_in[2];
    const float* Wn    = (const float*)d_in[3];
    const float* bn    = (const float*)d_in[4];
    const float* Wq    = (const float*)d_in[5];
    const float* bq    = (const float*)d_in[6];
    const float* Wk    = (const float*)d_in[7];
    const float* bk    = (const float*)d_in[8];
    const float* Wv    = (const float*)d_in[9];
    const float* bv    = (const float*)d_in[10];
    const float* We    = (const float*)d_in[11];
    const float* be    = (const float*)d_in[12];
    const float* A1    = (const float*)d_in[13];
    const float* a1    = (const float*)d_in[14];
    const float* A2    = (const float*)d_in[15];
    const float* a2    = (const float*)d_in[16];
    const float* gamma = (const float*)d_in[17];
    const float* beta  = (const float*)d_in[18];
    float* out = (float*)d_out;

    cudaFuncSetAttribute(k_node_gemm, cudaFuncAttributeMaxDynamicSharedMemorySize, NGM_SMEM);
    cudaFuncSetAttribute(k_edge, cudaFuncAttributeMaxDynamicSharedMemorySize, EDGE_SMEM);

    k_pre<<<4096, 256>>>(EI, Wn, bn, Wv, bv, A2, X);
    k_prep_fold<<<145, 256>>>(Wq, bq, Wk, bk, We, be, A1, a1);
    k_node_gemm<<<dim3(8, 128), 256, NGM_SMEM>>>();
    k_edge<<<2048, 256, EDGE_SMEM>>>(EF, EI, a2);     // launch #4 -> profiled
    k_scan<<<1, 1024>>>();
    k_place_ssum<<<1024, 256>>>(EI);
    k_final<<<16384, 128>>>(EI, gamma, beta, out);
}